// round 11
// baseline (speedup 1.0000x reference)
#include <cuda_runtime.h>
#include <cstdint>
#include <cstddef>

#define NN 32768
#define EE 262144

static const size_t O_OUT_V = (size_t)NN * 64;
static const size_t O_SC_S  = (size_t)NN * 256;
static const size_t O_SC_V  = (size_t)NN * 320;

typedef unsigned long long ull;

// ---------------- device scratch ----------------
__device__ float4 g_xq[(size_t)NN * 64];     // input pack: (xv0, xv1, xs, xv2)
__device__ float4 g_xq2[(size_t)NN * 64];    // self-mixed: (v0, v1, v2, s)
__device__ float  g_tpw[(size_t)EE * 320];
__device__ ull    g_wsv[640 * 64];           // packed (W_sc_s, W_sc_v)
__device__ float2 g_wself[64 * 64];          // packed (W_self_s, W_self_v)
__device__ ull    g_wms2[64 * 64];           // paired (Wms[2k][d], Wms[2k+1][d])
__device__ ull    g_wmv2[96 * 64];           // paired (Wmv[2k][d], Wmv[2k+1][d])
__device__ int    g_cnt[NN];
__device__ int    g_off[NN + 1];
__device__ int    g_woff[NN];
__device__ int    g_eord[EE];
__device__ int    g_bsum[32];
__device__ int    g_bpre[32];

// ---------------- helpers ----------------
__device__ __forceinline__ ull pk2(float lo, float hi) {
    ull r; asm("mov.b64 %0, {%1, %2};" : "=l"(r) : "f"(lo), "f"(hi)); return r;
}
__device__ __forceinline__ void upk2(ull v, float& lo, float& hi) {
    asm("mov.b64 {%0, %1}, %2;" : "=f"(lo), "=f"(hi) : "l"(v));
}
__device__ __forceinline__ ull ff2(ull a, ull b, ull c) {
    ull d; asm("fma.rn.f32x2 %0, %1, %2, %3;" : "=l"(d) : "l"(a), "l"(b), "l"(c));
    return d;
}
__device__ __forceinline__ float fold2(ull v) {
    float lo, hi; upk2(v, lo, hi); return lo + hi;
}
__device__ __forceinline__ float silu_f(float x) {
    return x * __fdividef(1.0f, 1.0f + __expf(-x));
}

// ============================================================================
// K_prep: pack weights; zero counters
// ============================================================================
__global__ void k_prep(const float* __restrict__ Wscs, const float* __restrict__ Wscv,
                       const float* __restrict__ Wss,  const float* __restrict__ Wsv,
                       const float* __restrict__ Wms,  const float* __restrict__ Wmv) {
    const int i = blockIdx.x * 256 + threadIdx.x;
    if (i < 640 * 64) g_wsv[i] = pk2(Wscs[i], Wscv[i]);
    if (i < 64 * 64)  g_wself[i] = make_float2(Wss[i], Wsv[i]);
    if (i < 64 * 64) {
        const int kp = i >> 6, d = i & 63;
        g_wms2[i] = pk2(Wms[(2 * kp) * 64 + d], Wms[(2 * kp + 1) * 64 + d]);
    }
    if (i < 96 * 64) {
        const int kp = i >> 6, d = i & 63;
        g_wmv2[i] = pk2(Wmv[(2 * kp) * 64 + d], Wmv[(2 * kp + 1) * 64 + d]);
    }
    if (i < NN) g_cnt[i] = 0;
}

// K_prepx: pack (xv0, xv1, xs, xv2); fused receiver histogram
__global__ void k_prepx(const float* __restrict__ xs_in,
                        const float* __restrict__ xv_in,
                        const int* __restrict__ recv) {
    const size_t i = (size_t)blockIdx.x * 256 + threadIdx.x;  // over N*C
    const float xs = xs_in[i];
    const float* p = xv_in + i * 3;
    g_xq[i] = make_float4(p[0], p[1], xs, p[2]);
    if (i < EE) atomicAdd(&g_cnt[recv[i]], 1);
}

// ============================================================================
// K2 (R8 config): edge MLP; hT[k][e] swizzled in smem; weights streamed from
// L2 via LDG; 128 threads/block, 128 edges/block; tile = 8 edges x 8 outputs;
// smem = 67584 B -> 3 blocks/SM (12 warps).
// ============================================================================
#define HPITCH 128

__device__ __forceinline__ void mlp_zero8(ull acc[8][4]) {
#pragma unroll
    for (int j = 0; j < 8; j++)
#pragma unroll
        for (int q = 0; q < 4; q++) acc[j][q] = 0ull;
}

__device__ __forceinline__ void mac8(
    ull acc[8][4], const float4 ha, const float4 hb,
    const ulonglong2 wa, const ulonglong2 wb)
{
    const float hv[8] = {ha.x, ha.y, ha.z, ha.w, hb.x, hb.y, hb.z, hb.w};
#pragma unroll
    for (int j = 0; j < 8; j++) {
        const ull p = pk2(hv[j], hv[j]);
        acc[j][0] = ff2(p, wa.x, acc[j][0]);
        acc[j][1] = ff2(p, wa.y, acc[j][1]);
        acc[j][2] = ff2(p, wb.x, acc[j][2]);
        acc[j][3] = ff2(p, wb.y, acc[j][3]);
    }
}

template <int WSTRIDE>
__device__ __forceinline__ void chunk64_g(
    const float* __restrict__ hSrc, const float* __restrict__ W,
    const int e0, const int og, ull acc[8][4])
{
    const float* wp = W + og * 8;
#pragma unroll 1
    for (int k8 = 0; k8 < 8; k8++) {
        const int cofs = e0 ^ (k8 << 4);
        const float* hp = hSrc + k8 * 8 * HPITCH + cofs;
        const float* wk = wp + k8 * 8 * WSTRIDE;
#pragma unroll
        for (int kk = 0; kk < 8; kk++) {
            const float4 ha = *(const float4*)(hp + kk * HPITCH);
            const float4 hb = *(const float4*)(hp + kk * HPITCH + 4);
            const ulonglong2 wa = __ldg((const ulonglong2*)(wk + kk * WSTRIDE));
            const ulonglong2 wb = __ldg((const ulonglong2*)(wk + kk * WSTRIDE + 4));
            mac8(acc, ha, hb, wa, wb);
        }
    }
}

__device__ __forceinline__ void store_h8(
    ull acc[8][4], float* __restrict__ hDst,
    const int e0, const int og, const float scale)
{
#pragma unroll
    for (int q = 0; q < 4; q++) {
        float l[8], h[8];
#pragma unroll
        for (int j = 0; j < 8; j++) upk2(acc[j][q], l[j], h[j]);
        const int k0 = og * 8 + 2 * q;    // k0>>3 == og
        const int k1 = k0 + 1;
        const int c0 = e0 ^ (og << 4);
        float* r0 = hDst + k0 * HPITCH + c0;
        float* r1 = hDst + k1 * HPITCH + c0;
        *(float4*)r0 =
            make_float4(silu_f(l[0] * scale), silu_f(l[1] * scale),
                        silu_f(l[2] * scale), silu_f(l[3] * scale));
        *(float4*)(r0 + 4) =
            make_float4(silu_f(l[4] * scale), silu_f(l[5] * scale),
                        silu_f(l[6] * scale), silu_f(l[7] * scale));
        *(float4*)r1 =
            make_float4(silu_f(h[0] * scale), silu_f(h[1] * scale),
                        silu_f(h[2] * scale), silu_f(h[3] * scale));
        *(float4*)(r1 + 4) =
            make_float4(silu_f(h[4] * scale), silu_f(h[5] * scale),
                        silu_f(h[6] * scale), silu_f(h[7] * scale));
    }
}

__global__ __launch_bounds__(128, 3) void k_mlp(
    const float* __restrict__ feats,
    const float* __restrict__ W0, const float* __restrict__ W1,
    const float* __restrict__ W2, const float* __restrict__ W3)
{
    extern __shared__ float sw[];
    float* sW0 = sw;             // [8][64]
    float* hA  = sw + 512;       // [64][128] transposed
    float* hB  = sw + 8704;      // [64][128] transposed

    const int t = threadIdx.x;
    for (int i = t; i < 512; i += 128) sW0[i] = W0[i];

    const size_t fbase = (size_t)blockIdx.x * 128 * 8;
    for (int i = t; i < 1024; i += 128)
        hA[(i & 7) * HPITCH + (i >> 3)] = feats[fbase + i];
    __syncthreads();

    const int og = t & 7;        // outputs og*8 .. +7
    const int e0 = (t >> 3) * 8; // edges e0 .. e0+7

    ull acc[8][4];

    // layer 0: K=8, scale 1/sqrt(8), silu -> hB
    {
        mlp_zero8(acc);
        const float* wp = sW0 + og * 8;
#pragma unroll
        for (int k = 0; k < 8; k++) {
            const float4 ha = *(const float4*)(hA + k * HPITCH + e0);
            const float4 hb = *(const float4*)(hA + k * HPITCH + e0 + 4);
            const ulonglong2 wa = *(const ulonglong2*)(wp + k * 64);
            const ulonglong2 wb = *(const ulonglong2*)(wp + k * 64 + 4);
            mac8(acc, ha, hb, wa, wb);
        }
        store_h8(acc, hB, e0, og, 0.3535533905932738f);
    }
    __syncthreads();

    // layer 1: hB -> hA  (W1 streamed from L2)
    mlp_zero8(acc);
    chunk64_g<64>(hB, W1, e0, og, acc);
    store_h8(acc, hA, e0, og, 0.125f);
    __syncthreads();

    // layer 2: hA -> hB  (W2 streamed from L2)
    mlp_zero8(acc);
    chunk64_g<64>(hA, W2, e0, og, acc);
    store_h8(acc, hB, e0, og, 0.125f);
    __syncthreads();

    // layer 3: hB -> g_tpw, 5 chunks of 64 outputs (W3 streamed from L2)
    const size_t tbase = (size_t)blockIdx.x * 128;
#pragma unroll 1
    for (int ch = 0; ch < 5; ch++) {
        mlp_zero8(acc);
        chunk64_g<320>(hB, W3 + ch * 64, e0, og, acc);
#pragma unroll
        for (int j = 0; j < 8; j++) {
            float l0, h0, l1, h1, l2, h2, l3, h3;
            upk2(acc[j][0], l0, h0); upk2(acc[j][1], l1, h1);
            upk2(acc[j][2], l2, h2); upk2(acc[j][3], l3, h3);
            float* op = g_tpw + (tbase + e0 + j) * 320 + ch * 64 + og * 8;
            *(float4*)op =
                make_float4(l0 * 0.125f, h0 * 0.125f, l1 * 0.125f, h1 * 0.125f);
            *(float4*)(op + 4) =
                make_float4(l2 * 0.125f, h2 * 0.125f, l3 * 0.125f, h3 * 0.125f);
        }
    }
}

// ============================================================================
// CSR build: hierarchical scan -> fill -> sort (count fused into k_prepx)
// ============================================================================
__global__ void k_scan_a() {      // grid 32, block 1024
    __shared__ int ss[1024];
    const int t = threadIdx.x;
    const int i = blockIdx.x * 1024 + t;
    const int v = g_cnt[i];
    ss[t] = v;
    __syncthreads();
    for (int dd = 1; dd < 1024; dd <<= 1) {
        const int u = (t >= dd) ? ss[t - dd] : 0;
        __syncthreads();
        ss[t] += u;
        __syncthreads();
    }
    g_off[i] = ss[t] - v;
    g_woff[i] = 0;
    if (t == 1023) g_bsum[blockIdx.x] = ss[t];
}
__global__ void k_scan_b() {      // 1 block, 32 threads
    const int t = threadIdx.x;
    const int orig = g_bsum[t];
    int v = orig;
    for (int dd = 1; dd < 32; dd <<= 1) {
        const int u = __shfl_up_sync(0xffffffffu, v, dd);
        if (t >= dd) v += u;
    }
    g_bpre[t] = v - orig;
    if (t == 31) g_off[NN] = v;
}
__global__ void k_scan_c() {      // grid 128 x 256
    const int i = blockIdx.x * 256 + threadIdx.x;
    g_off[i] += g_bpre[i >> 10];
}
__global__ void k_fill(const int* __restrict__ recv) {
    const int e = blockIdx.x * blockDim.x + threadIdx.x;
    if (e < EE) {
        const int r = recv[e];
        const int p = atomicAdd(&g_woff[r], 1);
        g_eord[g_off[r] + p] = e;
    }
}
__global__ void k_sort() {
    const int n = blockIdx.x * blockDim.x + threadIdx.x;
    if (n >= NN) return;
    const int s = g_off[n], e = g_off[n + 1];
    for (int i = s + 1; i < e; i++) {
        const int v = g_eord[i];
        int j = i - 1;
        while (j >= s && g_eord[j] > v) { g_eord[j + 1] = g_eord[j]; j--; }
        g_eord[j + 1] = v;
    }
}

// ============================================================================
// K1 v3: per-node sc_s/sc_v + self-mix; weights smem-stationary (LDS.128
// paired a-slices), packed-pair algebra; d-quartered.
// grid (128, 4) x 256 threads; dyn smem 90112 B    [profiled slot #4]
// ============================================================================
__global__ __launch_bounds__(256, 2) void k_node(
    const float* __restrict__ attr, float* __restrict__ out)
{
    extern __shared__ ull dynsm[];
    ulonglong2* swp   = (ulonglong2*)dynsm;        // [c*80 + a2*16 + d], 5120 ull2
    ull*        swsf  = dynsm + 10240;             // [c*16 + d] packed (ws, wv)

    const int t = threadIdx.x;
    const int dq = blockIdx.y;
    const int dd = dq * 16;

    for (int i = t; i < 5120; i += 256) {
        const int d_ = i & 15;
        const int r  = i >> 4;         // c*5 + a2
        const int a2 = r % 5;
        const int c  = r / 5;
        swp[i] = make_ulonglong2(
            g_wsv[(c * 10 + 2 * a2) * 64 + dd + d_],
            g_wsv[(c * 10 + 2 * a2 + 1) * 64 + dd + d_]);
    }
    for (int i = t; i < 1024; i += 256) {
        const int c = i >> 4, d_ = i & 15;
        const float2 w = g_wself[c * 64 + dd + d_];
        swsf[i] = pk2(w.x, w.y);
    }
    __syncthreads();

    const int d = t & 15, grp = t >> 4;
    const int nbase = blockIdx.x * 256 + grp * 16;
    const int D = dd + d;
    const float S640 = 0.039528470752104741f;  // 1/sqrt(640)

    for (int pass = 0; pass < 8; pass++) {
        const int nA = nbase + pass * 2;
        const int nB = nA + 1;

        ull aPA[10], aPB[10];
#pragma unroll
        for (int a = 0; a < 10; a++) {
            const float vA = __ldg(attr + (size_t)nA * 10 + a);
            const float vB = __ldg(attr + (size_t)nB * 10 + a);
            aPA[a] = pk2(vA, vA);
            aPB[a] = pk2(vB, vB);
        }

        // packed accumulators: (s, v2) channel pairs + (v0, v1) pairs
        ull sv2A = 0ull, sv2B = 0ull;       // mix apply
        ull sv2sA = 0ull, sv2sB = 0ull;     // self mix
        ull v01A = 0ull, v01B = 0ull;
        ull v01sA = 0ull, v01sB = 0ull;

        const float4* xqA = g_xq + (size_t)nA * 64;
        const float4* xqB = g_xq + (size_t)nB * 64;

#pragma unroll 2
        for (int c = 0; c < 64; c++) {
            const float4 xA = __ldg(xqA + c);   // (v0, v1, s, v2)
            const float4 xB = __ldg(xqB + c);
            const ull xyA = pk2(xA.x, xA.y);    // (v0, v1) reg pair
            const ull zwA = pk2(xA.z, xA.w);    // (s,  v2) reg pair
            const ull xyB = pk2(xB.x, xB.y);
            const ull zwB = pk2(xB.z, xB.w);

            const ull wsf = swsf[c * 16 + d];   // (ws, wv)
            float wsl, wvl; upk2(wsf, wsl, wvl);
            const ull wvd = pk2(wvl, wvl);

            sv2sA = ff2(zwA, wsf, sv2sA);       // (s*ws, v2*wv)
            v01sA = ff2(xyA, wvd, v01sA);
            sv2sB = ff2(zwB, wsf, sv2sB);
            v01sB = ff2(xyB, wvd, v01sB);

            ull mA = 0ull, mB = 0ull;           // (Ms, Mv)
            const ulonglong2* wp = swp + c * 80 + d;
#pragma unroll
            for (int a2 = 0; a2 < 5; a2++) {
                const ulonglong2 w = wp[a2 * 16];
                mA = ff2(aPA[2 * a2], w.x, mA);
                mA = ff2(aPA[2 * a2 + 1], w.y, mA);
                mB = ff2(aPB[2 * a2], w.x, mB);
                mB = ff2(aPB[2 * a2 + 1], w.y, mB);
            }

            sv2A = ff2(zwA, mA, sv2A);          // (s*Ms, v2*Mv) — mA used packed
            sv2B = ff2(zwB, mB, sv2B);
            float MsA, MvA, MsB, MvB;
            upk2(mA, MsA, MvA);
            upk2(mB, MsB, MvB);
            v01A = ff2(xyA, pk2(MvA, MvA), v01A);
            v01B = ff2(xyB, pk2(MvB, MvB), v01B);
        }

        // epilogue
        {
            float sA, v2A, v0A, v1A; upk2(sv2A, sA, v2A); upk2(v01A, v0A, v1A);
            float sB, v2B, v0B, v1B; upk2(sv2B, sB, v2B); upk2(v01B, v0B, v1B);
            out[O_SC_S + (size_t)nA * 64 + D] = sA * S640;
            out[O_SC_S + (size_t)nB * 64 + D] = sB * S640;
            const size_t vbA = O_SC_V + (size_t)nA * 192 + (size_t)D * 3;
            const size_t vbB = O_SC_V + (size_t)nB * 192 + (size_t)D * 3;
            out[vbA] = v0A * S640; out[vbA + 1] = v1A * S640; out[vbA + 2] = v2A * S640;
            out[vbB] = v0B * S640; out[vbB + 1] = v1B * S640; out[vbB + 2] = v2B * S640;

            float ssA, sv2cA, s0A, s1A; upk2(sv2sA, ssA, sv2cA); upk2(v01sA, s0A, s1A);
            float ssB, sv2cB, s0B, s1B; upk2(sv2sB, ssB, sv2cB); upk2(v01sB, s0B, s1B);
            g_xq2[(size_t)nA * 64 + D] =
                make_float4(s0A * 0.125f, s1A * 0.125f, sv2cA * 0.125f, ssA * 0.125f);
            g_xq2[(size_t)nB * 64 + D] =
                make_float4(s0B * 0.125f, s1B * 0.125f, sv2cB * 0.125f, ssB * 0.125f);
        }
    }
}

// ============================================================================
// K4 v3: gather aggregation + output GEMMs with weights amortized over the
// 4 node-groups (threads 0-63: out_s x4; threads 64-255: out_v (d,comp) x4).
// g_xq2 layout: (v0, v1, v2, s)
// ============================================================================
__global__ __launch_bounds__(256) void k_agg(
    const int* __restrict__ send, const float* __restrict__ eattr,
    float* __restrict__ out)
{
    __shared__ __align__(16) float sms[4][128];
    __shared__ __align__(16) float sv0[4][192];
    __shared__ __align__(16) float sv1[4][192];
    __shared__ __align__(16) float sv2[4][192];

    const int t = threadIdx.x;
    const int g = t >> 6, c = t & 63;
    const int nb = blockIdx.x * 4;
    const int n = nb + g;
    const int e0 = g_off[n], e1 = g_off[n + 1];

    float as0 = 0.f, as1 = 0.f;
    ull   av0_01 = 0ull, av1_01 = 0ull, av2_01 = 0ull;
    float av0_2 = 0.f, av1_2 = 0.f, av2_2 = 0.f;

    for (int p = e0; p < e1; p++) {
        const int e = g_eord[p];
        const int s = __ldg(send + e);
        const float4 ea = __ldg((const float4*)eattr + e);
        const float sh0 = ea.x, s1x = ea.y, s1y = ea.z, s1z = ea.w;
        const float* tp = g_tpw + (size_t)e * 320 + c;
        const float w0 = tp[0], w1 = tp[64], w2 = tp[128], w3 = tp[192], w4 = tp[256];
        const float4 xq = __ldg(g_xq2 + (size_t)s * 64 + c);
        const float xs = xq.w;

        as0 = fmaf(w0 * xs, sh0, as0);
        const float dt = xq.x * s1x + xq.y * s1y + xq.z * s1z;
        as1 = fmaf(w3, dt, as1);

        const float t1 = w1 * xs;
        av0_01 = ff2(pk2(t1, t1), pk2(s1x, s1y), av0_01);
        av0_2  = fmaf(t1, s1z, av0_2);

        const float w2sh = w2 * sh0;
        av1_01 = ff2(pk2(xq.x, xq.y), pk2(w2sh, w2sh), av1_01);
        av1_2  = fmaf(w2sh, xq.z, av1_2);

        const float cx = xq.y * s1z - xq.z * s1y;
        const float cy = xq.z * s1x - xq.x * s1z;
        const float cz = xq.x * s1y - xq.y * s1x;
        av2_01 = ff2(pk2(cx, cy), pk2(w4, w4), av2_01);
        av2_2  = fmaf(w4, cz, av2_2);
    }

    const float INV  = 0.3535533905932738f;            // 1/sqrt(8)
    const float INV3 = INV * 0.5773502691896258f;
    const float INV2 = INV * 0.7071067811865476f;
    sms[g][c]      = as0 * INV;
    sms[g][64 + c] = as1 * INV3;
    {
        float a, b;
        upk2(av0_01, a, b);
        sv0[g][c] = a * INV;  sv1[g][c] = b * INV;  sv2[g][c] = av0_2 * INV;
        upk2(av1_01, a, b);
        sv0[g][64 + c] = a * INV;  sv1[g][64 + c] = b * INV;
        sv2[g][64 + c] = av1_2 * INV;
        upk2(av2_01, a, b);
        sv0[g][128 + c] = a * INV2;  sv1[g][128 + c] = b * INV2;
        sv2[g][128 + c] = av2_2 * INV2;
    }
    __syncthreads();

    if (t < 64) {
        const int d = t;
        ull os[4] = {0ull, 0ull, 0ull, 0ull};
#pragma unroll 4
        for (int kp = 0; kp < 64; kp++) {
            const ull w = __ldg(g_wms2 + kp * 64 + d);
#pragma unroll
            for (int q = 0; q < 4; q++)
                os[q] = ff2(((const ull*)sms[q])[kp], w, os[q]);
        }
#pragma unroll
        for (int q = 0; q < 4; q++)
            out[(size_t)(nb + q) * 64 + d] = fold2(os[q]) * 0.08838834764831845f;
    } else {
        const int u = t - 64;
        const int d = u & 63;
        const int comp = u >> 6;  // 0,1,2
        const float* pl = (comp == 0) ? &sv0[0][0]
                        : (comp == 1) ? &sv1[0][0] : &sv2[0][0];
        ull ov[4] = {0ull, 0ull, 0ull, 0ull};
#pragma unroll 4
        for (int kp = 0; kp < 96; kp++) {
            const ull w = __ldg(g_wmv2 + kp * 64 + d);
#pragma unroll
            for (int q = 0; q < 4; q++)
                ov[q] = ff2(((const ull*)(pl + q * 192))[kp], w, ov[q]);
        }
        const float S192 = 0.07216878364870323f;  // 1/sqrt(192)
#pragma unroll
        for (int q = 0; q < 4; q++)
            out[O_OUT_V + (size_t)(nb + q) * 192 + (size_t)d * 3 + comp] =
                fold2(ov[q]) * S192;
    }
}

// ============================================================================
extern "C" void kernel_launch(void* const* d_in, const int* in_sizes, int n_in,
                              void* d_out, int out_size)
{
    const float* node_attrs = (const float*)d_in[0];
    const float* x_s        = (const float*)d_in[1];
    const float* x_v        = (const float*)d_in[2];
    const float* edge_attrs = (const float*)d_in[3];
    const float* edge_feats = (const float*)d_in[4];
    const int*   senders    = (const int*)d_in[5];
    const int*   receivers  = (const int*)d_in[6];
    const float* W_sc_s     = (const float*)d_in[7];
    const float* W_sc_v     = (const float*)d_in[8];
    const float* W_self_s   = (const float*)d_in[9];
    const float* W_self_v   = (const float*)d_in[10];
    const float* mlp_W0     = (const float*)d_in[11];
    const float* mlp_W1     = (const float*)d_in[12];
    const float* mlp_W2     = (const float*)d_in[13];
    const float* mlp_W3     = (const float*)d_in[14];
    const float* W_msg_s    = (const float*)d_in[15];
    const float* W_msg_v    = (const float*)d_in[16];
    float* out = (float*)d_out;

    const size_t mlp_smem  = (size_t)(512 + 2 * 64 * HPITCH) * sizeof(float); // 67584
    const size_t node_smem = (size_t)(10240 + 1024) * 8;                      // 90112
    cudaFuncSetAttribute(k_mlp, cudaFuncAttributeMaxDynamicSharedMemorySize,
                         (int)mlp_smem);
    cudaFuncSetAttribute(k_node, cudaFuncAttributeMaxDynamicSharedMemorySize,
                         (int)node_smem);

    k_prep<<<160, 256>>>(W_sc_s, W_sc_v, W_self_s, W_self_v, W_msg_s, W_msg_v);
    k_prepx<<<NN * 64 / 256, 256>>>(x_s, x_v, receivers);
    k_mlp<<<EE / 128, 128, mlp_smem>>>(edge_feats, mlp_W0, mlp_W1, mlp_W2, mlp_W3);
    k_node<<<dim3(128, 4), 256, node_smem>>>(node_attrs, out);   // profiled (#4)
    k_scan_a<<<32, 1024>>>();
    k_scan_b<<<1, 32>>>();
    k_scan_c<<<128, 256>>>();
    k_fill<<<EE / 256, 256>>>(receivers);
    k_sort<<<NN / 128, 128>>>();
    k_agg<<<NN / 4, 256>>>(senders, edge_attrs, out);
}

// round 12
// speedup vs baseline: 1.0557x; 1.0557x over previous
#include <cuda_runtime.h>
#include <cstdint>
#include <cstddef>

#define NN 32768
#define EE 262144

static const size_t O_OUT_V = (size_t)NN * 64;
static const size_t O_SC_S  = (size_t)NN * 256;
static const size_t O_SC_V  = (size_t)NN * 320;

typedef unsigned long long ull;

// ---------------- device scratch ----------------
__device__ float4 g_xq[(size_t)NN * 64];     // input pack: (xv0,xv1,xv2,xs)
__device__ float4 g_xq2[(size_t)NN * 64];    // self-mixed: (v0,v1,v2,s)
__device__ float  g_tpw[(size_t)EE * 320];
__device__ ull    g_wsv[640 * 64];           // packed (W_sc_s, W_sc_v)
__device__ float2 g_wself[64 * 64];          // packed (W_self_s, W_self_v)
__device__ ull    g_wms2[64 * 64];           // paired (Wms[2k][d], Wms[2k+1][d])
__device__ ull    g_wmv2[96 * 64];           // paired (Wmv[2k][d], Wmv[2k+1][d])
__device__ int    g_cnt[NN];
__device__ int    g_off[NN + 1];
__device__ int    g_woff[NN];
__device__ int    g_eord[EE];
__device__ int    g_bsum[32];
__device__ int    g_bpre[32];

// ---------------- helpers ----------------
__device__ __forceinline__ ull pk2(float lo, float hi) {
    ull r; asm("mov.b64 %0, {%1, %2};" : "=l"(r) : "f"(lo), "f"(hi)); return r;
}
__device__ __forceinline__ void upk2(ull v, float& lo, float& hi) {
    asm("mov.b64 {%0, %1}, %2;" : "=f"(lo), "=f"(hi) : "l"(v));
}
__device__ __forceinline__ ull ff2(ull a, ull b, ull c) {
    ull d; asm("fma.rn.f32x2 %0, %1, %2, %3;" : "=l"(d) : "l"(a), "l"(b), "l"(c));
    return d;
}
__device__ __forceinline__ float fold2(ull v) {
    float lo, hi; upk2(v, lo, hi); return lo + hi;
}
__device__ __forceinline__ float silu_f(float x) {
    return x * __fdividef(1.0f, 1.0f + __expf(-x));
}

// ============================================================================
// K_prep: pack weights; zero counters
// ============================================================================
__global__ void k_prep(const float* __restrict__ Wscs, const float* __restrict__ Wscv,
                       const float* __restrict__ Wss,  const float* __restrict__ Wsv,
                       const float* __restrict__ Wms,  const float* __restrict__ Wmv) {
    const int i = blockIdx.x * 256 + threadIdx.x;
    if (i < 640 * 64) g_wsv[i] = pk2(Wscs[i], Wscv[i]);
    if (i < 64 * 64)  g_wself[i] = make_float2(Wss[i], Wsv[i]);
    if (i < 64 * 64) {
        const int kp = i >> 6, d = i & 63;
        g_wms2[i] = pk2(Wms[(2 * kp) * 64 + d], Wms[(2 * kp + 1) * 64 + d]);
    }
    if (i < 96 * 64) {
        const int kp = i >> 6, d = i & 63;
        g_wmv2[i] = pk2(Wmv[(2 * kp) * 64 + d], Wmv[(2 * kp + 1) * 64 + d]);
    }
    if (i < NN) g_cnt[i] = 0;
}

// K_prepx: pack (x_v, x_s) into float4; fused receiver histogram
__global__ void k_prepx(const float* __restrict__ xs_in,
                        const float* __restrict__ xv_in,
                        const int* __restrict__ recv) {
    const size_t i = (size_t)blockIdx.x * 256 + threadIdx.x;  // over N*C
    const float xs = xs_in[i];
    const float* p = xv_in + i * 3;
    g_xq[i] = make_float4(p[0], p[1], p[2], xs);
    if (i < EE) atomicAdd(&g_cnt[recv[i]], 1);
}

// ============================================================================
// K2 (R8 config): edge MLP; hT[k][e] swizzled in smem; weights streamed from
// L2 via LDG; 128 threads/block, 128 edges/block; tile = 8 edges x 8 outputs;
// smem = 67584 B -> 3 blocks/SM (12 warps).
// ============================================================================
#define HPITCH 128

__device__ __forceinline__ void mlp_zero8(ull acc[8][4]) {
#pragma unroll
    for (int j = 0; j < 8; j++)
#pragma unroll
        for (int q = 0; q < 4; q++) acc[j][q] = 0ull;
}

__device__ __forceinline__ void mac8(
    ull acc[8][4], const float4 ha, const float4 hb,
    const ulonglong2 wa, const ulonglong2 wb)
{
    const float hv[8] = {ha.x, ha.y, ha.z, ha.w, hb.x, hb.y, hb.z, hb.w};
#pragma unroll
    for (int j = 0; j < 8; j++) {
        const ull p = pk2(hv[j], hv[j]);
        acc[j][0] = ff2(p, wa.x, acc[j][0]);
        acc[j][1] = ff2(p, wa.y, acc[j][1]);
        acc[j][2] = ff2(p, wb.x, acc[j][2]);
        acc[j][3] = ff2(p, wb.y, acc[j][3]);
    }
}

template <int WSTRIDE>
__device__ __forceinline__ void chunk64_g(
    const float* __restrict__ hSrc, const float* __restrict__ W,
    const int e0, const int og, ull acc[8][4])
{
    const float* wp = W + og * 8;
#pragma unroll 1
    for (int k8 = 0; k8 < 8; k8++) {
        const int cofs = e0 ^ (k8 << 4);
        const float* hp = hSrc + k8 * 8 * HPITCH + cofs;
        const float* wk = wp + k8 * 8 * WSTRIDE;
#pragma unroll
        for (int kk = 0; kk < 8; kk++) {
            const float4 ha = *(const float4*)(hp + kk * HPITCH);
            const float4 hb = *(const float4*)(hp + kk * HPITCH + 4);
            const ulonglong2 wa = __ldg((const ulonglong2*)(wk + kk * WSTRIDE));
            const ulonglong2 wb = __ldg((const ulonglong2*)(wk + kk * WSTRIDE + 4));
            mac8(acc, ha, hb, wa, wb);
        }
    }
}

__device__ __forceinline__ void store_h8(
    ull acc[8][4], float* __restrict__ hDst,
    const int e0, const int og, const float scale)
{
#pragma unroll
    for (int q = 0; q < 4; q++) {
        float l[8], h[8];
#pragma unroll
        for (int j = 0; j < 8; j++) upk2(acc[j][q], l[j], h[j]);
        const int k0 = og * 8 + 2 * q;    // k0>>3 == og
        const int k1 = k0 + 1;
        const int c0 = e0 ^ (og << 4);
        float* r0 = hDst + k0 * HPITCH + c0;
        float* r1 = hDst + k1 * HPITCH + c0;
        *(float4*)r0 =
            make_float4(silu_f(l[0] * scale), silu_f(l[1] * scale),
                        silu_f(l[2] * scale), silu_f(l[3] * scale));
        *(float4*)(r0 + 4) =
            make_float4(silu_f(l[4] * scale), silu_f(l[5] * scale),
                        silu_f(l[6] * scale), silu_f(l[7] * scale));
        *(float4*)r1 =
            make_float4(silu_f(h[0] * scale), silu_f(h[1] * scale),
                        silu_f(h[2] * scale), silu_f(h[3] * scale));
        *(float4*)(r1 + 4) =
            make_float4(silu_f(h[4] * scale), silu_f(h[5] * scale),
                        silu_f(h[6] * scale), silu_f(h[7] * scale));
    }
}

__global__ __launch_bounds__(128, 3) void k_mlp(
    const float* __restrict__ feats,
    const float* __restrict__ W0, const float* __restrict__ W1,
    const float* __restrict__ W2, const float* __restrict__ W3)
{
    extern __shared__ float sw[];
    float* sW0 = sw;             // [8][64]
    float* hA  = sw + 512;       // [64][128] transposed
    float* hB  = sw + 8704;      // [64][128] transposed

    const int t = threadIdx.x;
    for (int i = t; i < 512; i += 128) sW0[i] = W0[i];

    const size_t fbase = (size_t)blockIdx.x * 128 * 8;
    for (int i = t; i < 1024; i += 128)
        hA[(i & 7) * HPITCH + (i >> 3)] = feats[fbase + i];
    __syncthreads();

    const int og = t & 7;        // outputs og*8 .. +7
    const int e0 = (t >> 3) * 8; // edges e0 .. e0+7

    ull acc[8][4];

    // layer 0: K=8, scale 1/sqrt(8), silu -> hB
    {
        mlp_zero8(acc);
        const float* wp = sW0 + og * 8;
#pragma unroll
        for (int k = 0; k < 8; k++) {
            const float4 ha = *(const float4*)(hA + k * HPITCH + e0);
            const float4 hb = *(const float4*)(hA + k * HPITCH + e0 + 4);
            const ulonglong2 wa = *(const ulonglong2*)(wp + k * 64);
            const ulonglong2 wb = *(const ulonglong2*)(wp + k * 64 + 4);
            mac8(acc, ha, hb, wa, wb);
        }
        store_h8(acc, hB, e0, og, 0.3535533905932738f);
    }
    __syncthreads();

    // layer 1: hB -> hA  (W1 streamed from L2)
    mlp_zero8(acc);
    chunk64_g<64>(hB, W1, e0, og, acc);
    store_h8(acc, hA, e0, og, 0.125f);
    __syncthreads();

    // layer 2: hA -> hB  (W2 streamed from L2)
    mlp_zero8(acc);
    chunk64_g<64>(hA, W2, e0, og, acc);
    store_h8(acc, hB, e0, og, 0.125f);
    __syncthreads();

    // layer 3: hB -> g_tpw, 5 chunks of 64 outputs (W3 streamed from L2)
    const size_t tbase = (size_t)blockIdx.x * 128;
#pragma unroll 1
    for (int ch = 0; ch < 5; ch++) {
        mlp_zero8(acc);
        chunk64_g<320>(hB, W3 + ch * 64, e0, og, acc);
#pragma unroll
        for (int j = 0; j < 8; j++) {
            float l0, h0, l1, h1, l2, h2, l3, h3;
            upk2(acc[j][0], l0, h0); upk2(acc[j][1], l1, h1);
            upk2(acc[j][2], l2, h2); upk2(acc[j][3], l3, h3);
            float* op = g_tpw + (tbase + e0 + j) * 320 + ch * 64 + og * 8;
            *(float4*)op =
                make_float4(l0 * 0.125f, h0 * 0.125f, l1 * 0.125f, h1 * 0.125f);
            *(float4*)(op + 4) =
                make_float4(l2 * 0.125f, h2 * 0.125f, l3 * 0.125f, h3 * 0.125f);
        }
    }
}

// ============================================================================
// CSR build: hierarchical scan -> fill -> sort (count fused into k_prepx)
// ============================================================================
__global__ void k_scan_a() {      // grid 32, block 1024
    __shared__ int ss[1024];
    const int t = threadIdx.x;
    const int i = blockIdx.x * 1024 + t;
    const int v = g_cnt[i];
    ss[t] = v;
    __syncthreads();
    for (int dd = 1; dd < 1024; dd <<= 1) {
        const int u = (t >= dd) ? ss[t - dd] : 0;
        __syncthreads();
        ss[t] += u;
        __syncthreads();
    }
    g_off[i] = ss[t] - v;
    g_woff[i] = 0;
    if (t == 1023) g_bsum[blockIdx.x] = ss[t];
}
__global__ void k_scan_b() {      // 1 block, 32 threads
    const int t = threadIdx.x;
    const int orig = g_bsum[t];
    int v = orig;
    for (int dd = 1; dd < 32; dd <<= 1) {
        const int u = __shfl_up_sync(0xffffffffu, v, dd);
        if (t >= dd) v += u;
    }
    g_bpre[t] = v - orig;
    if (t == 31) g_off[NN] = v;
}
__global__ void k_scan_c() {      // grid 128 x 256
    const int i = blockIdx.x * 256 + threadIdx.x;
    g_off[i] += g_bpre[i >> 10];
}
__global__ void k_fill(const int* __restrict__ recv) {
    const int e = blockIdx.x * blockDim.x + threadIdx.x;
    if (e < EE) {
        const int r = recv[e];
        const int p = atomicAdd(&g_woff[r], 1);
        g_eord[g_off[r] + p] = e;
    }
}
__global__ void k_sort() {
    const int n = blockIdx.x * blockDim.x + threadIdx.x;
    if (n >= NN) return;
    const int s = g_off[n], e = g_off[n + 1];
    for (int i = s + 1; i < e; i++) {
        const int v = g_eord[i];
        int j = i - 1;
        while (j >= s && g_eord[j] > v) { g_eord[j + 1] = g_eord[j]; j--; }
        g_eord[j + 1] = v;
    }
}

// ============================================================================
// K1 (R10): per-node sc_s/sc_v + self-mix, weights smem-stationary,
// d-quartered. grid (128, 4) x 256 threads; dyn smem 90112 B
// ============================================================================
__global__ __launch_bounds__(256, 2) void k_node(
    const float* __restrict__ attr, float* __restrict__ out)
{
    extern __shared__ ull dynsm[];
    ull*    swsv   = dynsm;                        // [c*160 + a*16 + d]
    float2* swself = (float2*)(dynsm + 640 * 16);  // [c*16 + d]

    const int t = threadIdx.x;
    const int dq = blockIdx.y;
    const int dd = dq * 16;

    for (int i = t; i < 640 * 16; i += 256) {
        const int ca = i >> 4, d_ = i & 15;
        swsv[i] = g_wsv[ca * 64 + dd + d_];
    }
    for (int i = t; i < 64 * 16; i += 256) {
        const int c = i >> 4, d_ = i & 15;
        swself[i] = g_wself[c * 64 + dd + d_];
    }
    __syncthreads();

    const int d = t & 15, grp = t >> 4;
    const int nbase = blockIdx.x * 256 + grp * 16;
    const int D = dd + d;
    const float S640 = 0.039528470752104741f;  // 1/sqrt(640)

    for (int pass = 0; pass < 8; pass++) {
        const int nA = nbase + pass * 2;
        const int nB = nA + 1;

        ull aPA[10], aPB[10];
#pragma unroll
        for (int a = 0; a < 10; a++) {
            const float vA = __ldg(attr + (size_t)nA * 10 + a);
            const float vB = __ldg(attr + (size_t)nB * 10 + a);
            aPA[a] = pk2(vA, vA);
            aPB[a] = pk2(vB, vB);
        }

        float accS[2]  = {0.f, 0.f}, accS2[2] = {0.f, 0.f};
        float aV2[2]   = {0.f, 0.f}, aV2s[2]  = {0.f, 0.f};
        ull   aV01[2]  = {0ull, 0ull}, aV01s[2] = {0ull, 0ull};

        const float4* xqA = g_xq + (size_t)nA * 64;
        const float4* xqB = g_xq + (size_t)nB * 64;

#pragma unroll 2
        for (int c = 0; c < 64; c++) {
            const float4 xA = __ldg(xqA + c);
            const float4 xB = __ldg(xqB + c);
            const float2 wsf = swself[c * 16 + d];
            const ull wvd = pk2(wsf.y, wsf.y);

            accS2[0]  = fmaf(xA.w, wsf.x, accS2[0]);
            aV01s[0]  = ff2(pk2(xA.x, xA.y), wvd, aV01s[0]);
            aV2s[0]   = fmaf(xA.z, wsf.y, aV2s[0]);
            accS2[1]  = fmaf(xB.w, wsf.x, accS2[1]);
            aV01s[1]  = ff2(pk2(xB.x, xB.y), wvd, aV01s[1]);
            aV2s[1]   = fmaf(xB.z, wsf.y, aV2s[1]);

            ull mA = 0ull, mB = 0ull;
            const ull* wp = swsv + c * 160 + d;
#pragma unroll
            for (int a = 0; a < 10; a++) {
                const ull w = wp[a * 16];
                mA = ff2(aPA[a], w, mA);
                mB = ff2(aPB[a], w, mB);
            }
            float MsA, MvA, MsB, MvB;
            upk2(mA, MsA, MvA);
            upk2(mB, MsB, MvB);

            accS[0] = fmaf(xA.w, MsA, accS[0]);
            aV01[0] = ff2(pk2(xA.x, xA.y), pk2(MvA, MvA), aV01[0]);
            aV2[0]  = fmaf(xA.z, MvA, aV2[0]);
            accS[1] = fmaf(xB.w, MsB, accS[1]);
            aV01[1] = ff2(pk2(xB.x, xB.y), pk2(MvB, MvB), aV01[1]);
            aV2[1]  = fmaf(xB.z, MvB, aV2[1]);
        }

#pragma unroll
        for (int j = 0; j < 2; j++) {
            const int n = nA + j;
            out[O_SC_S + (size_t)n * 64 + D] = accS[j] * S640;
            float v0, v1; upk2(aV01[j], v0, v1);
            const size_t vb = O_SC_V + (size_t)n * 192 + (size_t)D * 3;
            out[vb]     = v0 * S640;
            out[vb + 1] = v1 * S640;
            out[vb + 2] = aV2[j] * S640;
            float s0, s1; upk2(aV01s[j], s0, s1);
            g_xq2[(size_t)n * 64 + D] =
                make_float4(s0 * 0.125f, s1 * 0.125f, aV2s[j] * 0.125f,
                            accS2[j] * 0.125f);
        }
    }
}

// ============================================================================
// K4 v3: gather aggregation + output GEMMs with weights amortized over the
// 4 node-groups (threads 0-63: out_s x4; threads 64-255: out_v (d,comp) x4).
// ============================================================================
__global__ __launch_bounds__(256) void k_agg(
    const int* __restrict__ send, const float* __restrict__ eattr,
    float* __restrict__ out)
{
    __shared__ __align__(16) float sms[4][128];
    __shared__ __align__(16) float sv0[4][192];
    __shared__ __align__(16) float sv1[4][192];
    __shared__ __align__(16) float sv2[4][192];

    const int t = threadIdx.x;
    const int g = t >> 6, c = t & 63;
    const int nb = blockIdx.x * 4;
    const int n = nb + g;
    const int e0 = g_off[n], e1 = g_off[n + 1];

    float as0 = 0.f, as1 = 0.f;
    ull   av0_01 = 0ull, av1_01 = 0ull, av2_01 = 0ull;
    float av0_2 = 0.f, av1_2 = 0.f, av2_2 = 0.f;

    for (int p = e0; p < e1; p++) {
        const int e = g_eord[p];
        const int s = __ldg(send + e);
        const float4 ea = __ldg((const float4*)eattr + e);
        const float sh0 = ea.x, s1x = ea.y, s1y = ea.z, s1z = ea.w;
        const float* tp = g_tpw + (size_t)e * 320 + c;
        const float w0 = tp[0], w1 = tp[64], w2 = tp[128], w3 = tp[192], w4 = tp[256];
        const float4 xq = __ldg(g_xq2 + (size_t)s * 64 + c);
        const float xs = xq.w;

        as0 = fmaf(w0 * xs, sh0, as0);
        const float dt = xq.x * s1x + xq.y * s1y + xq.z * s1z;
        as1 = fmaf(w3, dt, as1);

        const float t1 = w1 * xs;
        av0_01 = ff2(pk2(t1, t1), pk2(s1x, s1y), av0_01);
        av0_2  = fmaf(t1, s1z, av0_2);

        const float w2sh = w2 * sh0;
        av1_01 = ff2(pk2(xq.x, xq.y), pk2(w2sh, w2sh), av1_01);
        av1_2  = fmaf(w2sh, xq.z, av1_2);

        const float cx = xq.y * s1z - xq.z * s1y;
        const float cy = xq.z * s1x - xq.x * s1z;
        const float cz = xq.x * s1y - xq.y * s1x;
        av2_01 = ff2(pk2(cx, cy), pk2(w4, w4), av2_01);
        av2_2  = fmaf(w4, cz, av2_2);
    }

    const float INV  = 0.3535533905932738f;            // 1/sqrt(8)
    const float INV3 = INV * 0.5773502691896258f;
    const float INV2 = INV * 0.7071067811865476f;
    sms[g][c]      = as0 * INV;
    sms[g][64 + c] = as1 * INV3;
    {
        float a, b;
        upk2(av0_01, a, b);
        sv0[g][c] = a * INV;  sv1[g][c] = b * INV;  sv2[g][c] = av0_2 * INV;
        upk2(av1_01, a, b);
        sv0[g][64 + c] = a * INV;  sv1[g][64 + c] = b * INV;
        sv2[g][64 + c] = av1_2 * INV;
        upk2(av2_01, a, b);
        sv0[g][128 + c] = a * INV2;  sv1[g][128 + c] = b * INV2;
        sv2[g][128 + c] = av2_2 * INV2;
    }
    __syncthreads();

    if (t < 64) {
        const int d = t;
        ull os[4] = {0ull, 0ull, 0ull, 0ull};
#pragma unroll 4
        for (int kp = 0; kp < 64; kp++) {
            const ull w = __ldg(g_wms2 + kp * 64 + d);
#pragma unroll
            for (int q = 0; q < 4; q++)
                os[q] = ff2(((const ull*)sms[q])[kp], w, os[q]);
        }
#pragma unroll
        for (int q = 0; q < 4; q++)
            out[(size_t)(nb + q) * 64 + d] = fold2(os[q]) * 0.08838834764831845f;
    } else {
        const int u = t - 64;
        const int d = u & 63;
        const int comp = u >> 6;  // 0,1,2
        const float* pl = (comp == 0) ? &sv0[0][0]
                        : (comp == 1) ? &sv1[0][0] : &sv2[0][0];
        ull ov[4] = {0ull, 0ull, 0ull, 0ull};
#pragma unroll 4
        for (int kp = 0; kp < 96; kp++) {
            const ull w = __ldg(g_wmv2 + kp * 64 + d);
#pragma unroll
            for (int q = 0; q < 4; q++)
                ov[q] = ff2(((const ull*)(pl + q * 192))[kp], w, ov[q]);
        }
        const float S192 = 0.07216878364870323f;  // 1/sqrt(192)
#pragma unroll
        for (int q = 0; q < 4; q++)
            out[O_OUT_V + (size_t)(nb + q) * 192 + (size_t)d * 3 + comp] =
                fold2(ov[q]) * S192;
    }
}

// ============================================================================
// kernel_launch: fork-join graph — branch A: k_mlp; branch B: prep/prepx/
// node/CSR. Join before k_agg. Streams/events are created once (host-side).
// ============================================================================
extern "C" void kernel_launch(void* const* d_in, const int* in_sizes, int n_in,
                              void* d_out, int out_size)
{
    const float* node_attrs = (const float*)d_in[0];
    const float* x_s        = (const float*)d_in[1];
    const float* x_v        = (const float*)d_in[2];
    const float* edge_attrs = (const float*)d_in[3];
    const float* edge_feats = (const float*)d_in[4];
    const int*   senders    = (const int*)d_in[5];
    const int*   receivers  = (const int*)d_in[6];
    const float* W_sc_s     = (const float*)d_in[7];
    const float* W_sc_v     = (const float*)d_in[8];
    const float* W_self_s   = (const float*)d_in[9];
    const float* W_self_v   = (const float*)d_in[10];
    const float* mlp_W0     = (const float*)d_in[11];
    const float* mlp_W1     = (const float*)d_in[12];
    const float* mlp_W2     = (const float*)d_in[13];
    const float* mlp_W3     = (const float*)d_in[14];
    const float* W_msg_s    = (const float*)d_in[15];
    const float* W_msg_v    = (const float*)d_in[16];
    float* out = (float*)d_out;

    static cudaStream_t s1 = nullptr;
    static cudaEvent_t evFork = nullptr, evJoin = nullptr;
    static bool init_done = false;
    if (!init_done) {
        cudaStreamCreateWithFlags(&s1, cudaStreamNonBlocking);
        cudaEventCreateWithFlags(&evFork, cudaEventDisableTiming);
        cudaEventCreateWithFlags(&evJoin, cudaEventDisableTiming);
        const size_t mlp_smem_i  = (size_t)(512 + 2 * 64 * HPITCH) * sizeof(float);
        const size_t node_smem_i = (size_t)(640 * 16) * 8 + (size_t)(64 * 16) * 8;
        cudaFuncSetAttribute(k_mlp, cudaFuncAttributeMaxDynamicSharedMemorySize,
                             (int)mlp_smem_i);
        cudaFuncSetAttribute(k_node, cudaFuncAttributeMaxDynamicSharedMemorySize,
                             (int)node_smem_i);
        init_done = true;
    }

    const size_t mlp_smem  = (size_t)(512 + 2 * 64 * HPITCH) * sizeof(float); // 67584
    const size_t node_smem = (size_t)(640 * 16) * 8 + (size_t)(64 * 16) * 8;  // 90112

    // fork point (default stream)
    cudaEventRecord(evFork, 0);

    // branch A (default stream): the long edge MLP
    k_mlp<<<EE / 128, 128, mlp_smem, 0>>>(edge_feats, mlp_W0, mlp_W1,
                                          mlp_W2, mlp_W3);

    // branch B (s1): weight prep -> input pack+count -> node kernel -> CSR
    cudaStreamWaitEvent(s1, evFork, 0);
    k_prep<<<160, 256, 0, s1>>>(W_sc_s, W_sc_v, W_self_s, W_self_v,
                                W_msg_s, W_msg_v);
    k_prepx<<<NN * 64 / 256, 256, 0, s1>>>(x_s, x_v, receivers);
    k_node<<<dim3(128, 4), 256, node_smem, s1>>>(node_attrs, out);
    k_scan_a<<<32, 1024, 0, s1>>>();
    k_scan_b<<<1, 32, 0, s1>>>();
    k_scan_c<<<128, 256, 0, s1>>>();
    k_fill<<<EE / 256, 256, 0, s1>>>(receivers);
    k_sort<<<NN / 128, 128, 0, s1>>>();
    cudaEventRecord(evJoin, s1);

    // join, then the gather/output kernel
    cudaStreamWaitEvent(0, evJoin, 0);
    k_agg<<<NN / 4, 256, 0, 0>>>(senders, edge_attrs, out);
}

// round 14
// speedup vs baseline: 1.1482x; 1.0876x over previous
#include <cuda_runtime.h>
#include <cuda_bf16.h>
#include <cstdint>
#include <cstddef>

#define NN 32768
#define EE 262144

static const size_t O_OUT_V = (size_t)NN * 64;
static const size_t O_SC_S  = (size_t)NN * 256;
static const size_t O_SC_V  = (size_t)NN * 320;

typedef unsigned long long ull;

// ---------------- device scratch ----------------
__device__ float4 g_xq[(size_t)NN * 64];     // input pack: (xv0,xv1,xv2,xs)
__device__ float4 g_xq2[(size_t)NN * 64];    // self-mixed: (v0,v1,v2,s)
__device__ float  g_tpw[(size_t)EE * 320];
__device__ ull    g_wsv[640 * 64];           // packed (W_sc_s, W_sc_v)
__device__ float2 g_wself[64 * 64];          // packed (W_self_s, W_self_v)
__device__ ull    g_wms2[64 * 64];           // paired (Wms[2k][d], Wms[2k+1][d])
__device__ ull    g_wmv2[96 * 64];           // paired (Wmv[2k][d], Wmv[2k+1][d])
// bf16 hi/lo transposed MLP weights [n][k]
__device__ __align__(16) __nv_bfloat16 g_b1h[4096], g_b1l[4096];
__device__ __align__(16) __nv_bfloat16 g_b2h[4096], g_b2l[4096];
__device__ __align__(16) __nv_bfloat16 g_b3h[20480], g_b3l[20480];
__device__ int    g_cnt[NN];
__device__ int    g_off[NN + 1];
__device__ int    g_woff[NN];
__device__ int    g_eord[EE];
__device__ int    g_bsum[32];
__device__ int    g_bpre[32];

// ---------------- helpers ----------------
__device__ __forceinline__ ull pk2(float lo, float hi) {
    ull r; asm("mov.b64 %0, {%1, %2};" : "=l"(r) : "f"(lo), "f"(hi)); return r;
}
__device__ __forceinline__ void upk2(ull v, float& lo, float& hi) {
    asm("mov.b64 {%0, %1}, %2;" : "=f"(lo), "=f"(hi) : "l"(v));
}
__device__ __forceinline__ ull ff2(ull a, ull b, ull c) {
    ull d; asm("fma.rn.f32x2 %0, %1, %2, %3;" : "=l"(d) : "l"(a), "l"(b), "l"(c));
    return d;
}
__device__ __forceinline__ float fold2(ull v) {
    float lo, hi; upk2(v, lo, hi); return lo + hi;
}
__device__ __forceinline__ float silu_f(float x) {
    return x * __fdividef(1.0f, 1.0f + __expf(-x));
}
// split float pair (even,odd cols) into bf16 hi-pack and lo-residual-pack.
// low 16 bits hold the even-col element (matches mma fragment element order).
__device__ __forceinline__ void splitpack(float a, float b, uint32_t& hi, uint32_t& lo) {
    __nv_bfloat16 ah = __float2bfloat16(a), bh = __float2bfloat16(b);
    hi = ((uint32_t)__bfloat16_as_ushort(bh) << 16) | __bfloat16_as_ushort(ah);
    __nv_bfloat16 al = __float2bfloat16(a - __bfloat162float(ah));
    __nv_bfloat16 bl = __float2bfloat16(b - __bfloat162float(bh));
    lo = ((uint32_t)__bfloat16_as_ushort(bl) << 16) | __bfloat16_as_ushort(al);
}
// warp MMA m16n8k16 row.col bf16 -> f32 accumulate
__device__ __forceinline__ void mma_bf16(float d[4], const uint32_t a[4],
                                         const uint32_t b0, const uint32_t b1) {
    asm volatile(
        "mma.sync.aligned.m16n8k16.row.col.f32.bf16.bf16.f32 "
        "{%0,%1,%2,%3}, {%4,%5,%6,%7}, {%8,%9}, {%0,%1,%2,%3};"
        : "+f"(d[0]), "+f"(d[1]), "+f"(d[2]), "+f"(d[3])
        : "r"(a[0]), "r"(a[1]), "r"(a[2]), "r"(a[3]), "r"(b0), "r"(b1));
}

// ============================================================================
// K_prep: pack weights (node, self, output GEMM) + bf16 hi/lo transposed MLP
// ============================================================================
__global__ void k_prep(const float* __restrict__ Wscs, const float* __restrict__ Wscv,
                       const float* __restrict__ Wss,  const float* __restrict__ Wsv,
                       const float* __restrict__ Wms,  const float* __restrict__ Wmv,
                       const float* __restrict__ W1,   const float* __restrict__ W2,
                       const float* __restrict__ W3) {
    const int i = blockIdx.x * 256 + threadIdx.x;
    if (i < 640 * 64) g_wsv[i] = pk2(Wscs[i], Wscv[i]);
    if (i < 64 * 64)  g_wself[i] = make_float2(Wss[i], Wsv[i]);
    if (i < 64 * 64) {
        const int kp = i >> 6, d = i & 63;
        g_wms2[i] = pk2(Wms[(2 * kp) * 64 + d], Wms[(2 * kp + 1) * 64 + d]);
    }
    if (i < 96 * 64) {
        const int kp = i >> 6, d = i & 63;
        g_wmv2[i] = pk2(Wmv[(2 * kp) * 64 + d], Wmv[(2 * kp + 1) * 64 + d]);
    }
    if (i < 4096) {
        const int k = i >> 6, n = i & 63;
        float w = W1[i];
        __nv_bfloat16 h = __float2bfloat16(w);
        g_b1h[n * 64 + k] = h;
        g_b1l[n * 64 + k] = __float2bfloat16(w - __bfloat162float(h));
        w = W2[i];
        h = __float2bfloat16(w);
        g_b2h[n * 64 + k] = h;
        g_b2l[n * 64 + k] = __float2bfloat16(w - __bfloat162float(h));
    }
    if (i < 20480) {
        const int k = i / 320, n = i % 320;
        const float w = W3[i];
        const __nv_bfloat16 h = __float2bfloat16(w);
        g_b3h[n * 64 + k] = h;
        g_b3l[n * 64 + k] = __float2bfloat16(w - __bfloat162float(h));
    }
    if (i < NN) g_cnt[i] = 0;
}

// K_prepx: pack (x_v, x_s) into float4; fused receiver histogram
__global__ void k_prepx(const float* __restrict__ xs_in,
                        const float* __restrict__ xv_in,
                        const int* __restrict__ recv) {
    const size_t i = (size_t)blockIdx.x * 256 + threadIdx.x;  // over N*C
    const float xs = xs_in[i];
    const float* p = xv_in + i * 3;
    g_xq[i] = make_float4(p[0], p[1], p[2], xs);
    if (i < EE) atomicAdd(&g_cnt[recv[i]], 1);
}

// ============================================================================
// K2 v8: HMMA (mma.sync bf16 hi+lo split) edge MLP, register-chained layers.
// 128 edges/block, 128 threads (4 warps x 32 edges). W1/W2 in smem (pitch 72),
// W3 streamed from L2. Fragments never leave registers between layers.
// ============================================================================
#define WPITCH 72  // bf16 row pitch: 144 B -> 36-word stride (conflict-free)

__global__ __launch_bounds__(128, 3) void k_mlp(
    const float* __restrict__ feats, const float* __restrict__ W0)
{
    __shared__ float sW0[512];
    __shared__ __nv_bfloat16 sW1h[64 * WPITCH], sW1l[64 * WPITCH];
    __shared__ __nv_bfloat16 sW2h[64 * WPITCH], sW2l[64 * WPITCH];
    __shared__ float sF[1024];

    const int t = threadIdx.x;
    const int warp = t >> 5, lane = t & 31;
    const int t4 = lane & 3, gid = lane >> 2;

    for (int i = t; i < 512; i += 128) sW0[i] = W0[i];
    for (int i = t; i < 4096; i += 128) {
        const int n = i >> 6, k = i & 63;
        sW1h[n * WPITCH + k] = g_b1h[i];
        sW1l[n * WPITCH + k] = g_b1l[i];
        sW2h[n * WPITCH + k] = g_b2h[i];
        sW2l[n * WPITCH + k] = g_b2l[i];
    }
    const size_t fbase = (size_t)blockIdx.x * 1024;
    for (int i = t; i < 1024; i += 128) sF[i] = feats[fbase + i];  // [e][k]
    __syncthreads();

    // -------- layer 0: scalar K=8, results written directly as A fragments
    // A reg layout per 16x16 k-tile: reg0=(row gid,  k 2t4..+1)
    //                                reg1=(row gid+8,k 2t4..+1)
    //                                reg2=(row gid,  k 8+2t4..+1)
    //                                reg3=(row gid+8,k 8+2t4..+1)
    uint32_t Ah[2][4][4], Al[2][4][4];   // [mtile][ktile][reg]
#pragma unroll
    for (int mt = 0; mt < 2; mt++) {
#pragma unroll
        for (int row = 0; row < 2; row++) {
            const int el = warp * 32 + mt * 16 + row * 8 + gid;
            const float* f = sF + el * 8;
            float fr[8];
#pragma unroll
            for (int k = 0; k < 8; k++) fr[k] = f[k];
#pragma unroll
            for (int kt = 0; kt < 4; kt++) {
#pragma unroll
                for (int b = 0; b < 2; b++) {
                    const int c0 = kt * 16 + b * 8 + t4 * 2;
                    float h0 = 0.f, h1 = 0.f;
#pragma unroll
                    for (int k = 0; k < 8; k++) {
                        h0 = fmaf(fr[k], sW0[k * 64 + c0], h0);
                        h1 = fmaf(fr[k], sW0[k * 64 + c0 + 1], h1);
                    }
                    h0 = silu_f(h0 * 0.3535533905932738f);
                    h1 = silu_f(h1 * 0.3535533905932738f);
                    splitpack(h0, h1, Ah[mt][kt][row + 2 * b],
                                       Al[mt][kt][row + 2 * b]);
                }
            }
        }
    }

    float D[2][8][4];

    // -------- layers 1 and 2 (64->64, silu(x/8)), weights from smem
#pragma unroll 1
    for (int L = 0; L < 2; L++) {
        const __nv_bfloat16* Wh = L ? sW2h : sW1h;
        const __nv_bfloat16* Wl = L ? sW2l : sW1l;
#pragma unroll
        for (int mt = 0; mt < 2; mt++)
#pragma unroll
            for (int nt = 0; nt < 8; nt++)
#pragma unroll
                for (int q = 0; q < 4; q++) D[mt][nt][q] = 0.f;

#pragma unroll
        for (int nt = 0; nt < 8; nt++) {
            const uint32_t* ph = (const uint32_t*)(Wh + (nt * 8 + gid) * WPITCH);
            const uint32_t* pl = (const uint32_t*)(Wl + (nt * 8 + gid) * WPITCH);
            uint32_t bh[4][2], bl[4][2];
#pragma unroll
            for (int kt = 0; kt < 4; kt++) {
                bh[kt][0] = ph[kt * 8 + t4];  bh[kt][1] = ph[kt * 8 + t4 + 4];
                bl[kt][0] = pl[kt * 8 + t4];  bl[kt][1] = pl[kt * 8 + t4 + 4];
            }
#pragma unroll
            for (int mt = 0; mt < 2; mt++)
#pragma unroll
                for (int kt = 0; kt < 4; kt++) {
                    mma_bf16(D[mt][nt], Ah[mt][kt], bh[kt][0], bh[kt][1]);
                    mma_bf16(D[mt][nt], Ah[mt][kt], bl[kt][0], bl[kt][1]);
                    mma_bf16(D[mt][nt], Al[mt][kt], bh[kt][0], bh[kt][1]);
                }
        }

        // epilogue: silu + re-split into next A fragments (register chaining)
#pragma unroll
        for (int mt = 0; mt < 2; mt++)
#pragma unroll
            for (int kt = 0; kt < 4; kt++) {
                const float* da = D[mt][2 * kt];
                const float* db = D[mt][2 * kt + 1];
                float v0 = silu_f(da[0] * 0.125f), v1 = silu_f(da[1] * 0.125f);
                splitpack(v0, v1, Ah[mt][kt][0], Al[mt][kt][0]);
                v0 = silu_f(da[2] * 0.125f); v1 = silu_f(da[3] * 0.125f);
                splitpack(v0, v1, Ah[mt][kt][1], Al[mt][kt][1]);
                v0 = silu_f(db[0] * 0.125f); v1 = silu_f(db[1] * 0.125f);
                splitpack(v0, v1, Ah[mt][kt][2], Al[mt][kt][2]);
                v0 = silu_f(db[2] * 0.125f); v1 = silu_f(db[3] * 0.125f);
                splitpack(v0, v1, Ah[mt][kt][3], Al[mt][kt][3]);
            }
    }

    // -------- layer 3 (64 -> 320, x/8), 5 chunks of 64; weights from L2
    const int eb = blockIdx.x * 128 + warp * 32;
#pragma unroll 1
    for (int ch = 0; ch < 5; ch++) {
#pragma unroll
        for (int mt = 0; mt < 2; mt++)
#pragma unroll
            for (int nt = 0; nt < 8; nt++)
#pragma unroll
                for (int q = 0; q < 4; q++) D[mt][nt][q] = 0.f;

#pragma unroll
        for (int nt = 0; nt < 8; nt++) {
            const int n = ch * 64 + nt * 8 + gid;
            const uint32_t* ph = (const uint32_t*)(g_b3h + n * 64);
            const uint32_t* pl = (const uint32_t*)(g_b3l + n * 64);
            uint32_t bh[4][2], bl[4][2];
#pragma unroll
            for (int kt = 0; kt < 4; kt++) {
                bh[kt][0] = __ldg(ph + kt * 8 + t4);
                bh[kt][1] = __ldg(ph + kt * 8 + t4 + 4);
                bl[kt][0] = __ldg(pl + kt * 8 + t4);
                bl[kt][1] = __ldg(pl + kt * 8 + t4 + 4);
            }
#pragma unroll
            for (int mt = 0; mt < 2; mt++)
#pragma unroll
                for (int kt = 0; kt < 4; kt++) {
                    mma_bf16(D[mt][nt], Ah[mt][kt], bh[kt][0], bh[kt][1]);
                    mma_bf16(D[mt][nt], Ah[mt][kt], bl[kt][0], bl[kt][1]);
                    mma_bf16(D[mt][nt], Al[mt][kt], bh[kt][0], bh[kt][1]);
                }
        }

        // store: d0,d1 -> row gid; d2,d3 -> row gid+8 (x/8, no silu)
#pragma unroll
        for (int mt = 0; mt < 2; mt++) {
            const int e0 = eb + mt * 16 + gid;
#pragma unroll
            for (int nt = 0; nt < 8; nt++) {
                const int col = ch * 64 + nt * 8 + t4 * 2;
                const float* d = D[mt][nt];
                *(float2*)(g_tpw + (size_t)e0 * 320 + col) =
                    make_float2(d[0] * 0.125f, d[1] * 0.125f);
                *(float2*)(g_tpw + (size_t)(e0 + 8) * 320 + col) =
                    make_float2(d[2] * 0.125f, d[3] * 0.125f);
            }
        }
    }
}

// ============================================================================
// CSR build: hierarchical scan -> fill -> sort (count fused into k_prepx)
// ============================================================================
__global__ void k_scan_a() {      // grid 32, block 1024
    __shared__ int ss[1024];
    const int t = threadIdx.x;
    const int i = blockIdx.x * 1024 + t;
    const int v = g_cnt[i];
    ss[t] = v;
    __syncthreads();
    for (int dd = 1; dd < 1024; dd <<= 1) {
        const int u = (t >= dd) ? ss[t - dd] : 0;
        __syncthreads();
        ss[t] += u;
        __syncthreads();
    }
    g_off[i] = ss[t] - v;
    g_woff[i] = 0;
    if (t == 1023) g_bsum[blockIdx.x] = ss[t];
}
__global__ void k_scan_b() {      // 1 block, 32 threads
    const int t = threadIdx.x;
    const int orig = g_bsum[t];
    int v = orig;
    for (int dd = 1; dd < 32; dd <<= 1) {
        const int u = __shfl_up_sync(0xffffffffu, v, dd);
        if (t >= dd) v += u;
    }
    g_bpre[t] = v - orig;
    if (t == 31) g_off[NN] = v;
}
__global__ void k_scan_c() {      // grid 128 x 256
    const int i = blockIdx.x * 256 + threadIdx.x;
    g_off[i] += g_bpre[i >> 10];
}
__global__ void k_fill(const int* __restrict__ recv) {
    const int e = blockIdx.x * blockDim.x + threadIdx.x;
    if (e < EE) {
        const int r = recv[e];
        const int p = atomicAdd(&g_woff[r], 1);
        g_eord[g_off[r] + p] = e;
    }
}
__global__ void k_sort() {
    const int n = blockIdx.x * blockDim.x + threadIdx.x;
    if (n >= NN) return;
    const int s = g_off[n], e = g_off[n + 1];
    for (int i = s + 1; i < e; i++) {
        const int v = g_eord[i];
        int j = i - 1;
        while (j >= s && g_eord[j] > v) { g_eord[j + 1] = g_eord[j]; j--; }
        g_eord[j + 1] = v;
    }
}

// ============================================================================
// K1 (R10): per-node sc_s/sc_v + self-mix, weights smem-stationary,
// d-quartered. grid (128, 4) x 256 threads; dyn smem 90112 B
// ============================================================================
__global__ __launch_bounds__(256, 2) void k_node(
    const float* __restrict__ attr, float* __restrict__ out)
{
    extern __shared__ ull dynsm[];
    ull*    swsv   = dynsm;                        // [c*160 + a*16 + d]
    float2* swself = (float2*)(dynsm + 640 * 16);  // [c*16 + d]

    const int t = threadIdx.x;
    const int dq = blockIdx.y;
    const int dd = dq * 16;

    for (int i = t; i < 640 * 16; i += 256) {
        const int ca = i >> 4, d_ = i & 15;
        swsv[i] = g_wsv[ca * 64 + dd + d_];
    }
    for (int i = t; i < 64 * 16; i += 256) {
        const int c = i >> 4, d_ = i & 15;
        swself[i] = g_wself[c * 64 + dd + d_];
    }
    __syncthreads();

    const int d = t & 15, grp = t >> 4;
    const int nbase = blockIdx.x * 256 + grp * 16;
    const int D_ = dd + d;
    const float S640 = 0.039528470752104741f;  // 1/sqrt(640)

    for (int pass = 0; pass < 8; pass++) {
        const int nA = nbase + pass * 2;
        const int nB = nA + 1;

        ull aPA[10], aPB[10];
#pragma unroll
        for (int a = 0; a < 10; a++) {
            const float vA = __ldg(attr + (size_t)nA * 10 + a);
            const float vB = __ldg(attr + (size_t)nB * 10 + a);
            aPA[a] = pk2(vA, vA);
            aPB[a] = pk2(vB, vB);
        }

        float accS[2]  = {0.f, 0.f}, accS2[2] = {0.f, 0.f};
        float aV2[2]   = {0.f, 0.f}, aV2s[2]  = {0.f, 0.f};
        ull   aV01[2]  = {0ull, 0ull}, aV01s[2] = {0ull, 0ull};

        const float4* xqA = g_xq + (size_t)nA * 64;
        const float4* xqB = g_xq + (size_t)nB * 64;

#pragma unroll 2
        for (int c = 0; c < 64; c++) {
            const float4 xA = __ldg(xqA + c);
            const float4 xB = __ldg(xqB + c);
            const float2 wsf = swself[c * 16 + d];
            const ull wvd = pk2(wsf.y, wsf.y);

            accS2[0]  = fmaf(xA.w, wsf.x, accS2[0]);
            aV01s[0]  = ff2(pk2(xA.x, xA.y), wvd, aV01s[0]);
            aV2s[0]   = fmaf(xA.z, wsf.y, aV2s[0]);
            accS2[1]  = fmaf(xB.w, wsf.x, accS2[1]);
            aV01s[1]  = ff2(pk2(xB.x, xB.y), wvd, aV01s[1]);
            aV2s[1]   = fmaf(xB.z, wsf.y, aV2s[1]);

            ull mA = 0ull, mB = 0ull;
            const ull* wp = swsv + c * 160 + d;
#pragma unroll
            for (int a = 0; a < 10; a++) {
                const ull w = wp[a * 16];
                mA = ff2(aPA[a], w, mA);
                mB = ff2(aPB[a], w, mB);
            }
            float MsA, MvA, MsB, MvB;
            upk2(mA, MsA, MvA);
            upk2(mB, MsB, MvB);

            accS[0] = fmaf(xA.w, MsA, accS[0]);
            aV01[0] = ff2(pk2(xA.x, xA.y), pk2(MvA, MvA), aV01[0]);
            aV2[0]  = fmaf(xA.z, MvA, aV2[0]);
            accS[1] = fmaf(xB.w, MsB, accS[1]);
            aV01[1] = ff2(pk2(xB.x, xB.y), pk2(MvB, MvB), aV01[1]);
            aV2[1]  = fmaf(xB.z, MvB, aV2[1]);
        }

#pragma unroll
        for (int j = 0; j < 2; j++) {
            const int n = nA + j;
            out[O_SC_S + (size_t)n * 64 + D_] = accS[j] * S640;
            float v0, v1; upk2(aV01[j], v0, v1);
            const size_t vb = O_SC_V + (size_t)n * 192 + (size_t)D_ * 3;
            out[vb]     = v0 * S640;
            out[vb + 1] = v1 * S640;
            out[vb + 2] = aV2[j] * S640;
            float s0, s1; upk2(aV01s[j], s0, s1);
            g_xq2[(size_t)n * 64 + D_] =
                make_float4(s0 * 0.125f, s1 * 0.125f, aV2s[j] * 0.125f,
                            accS2[j] * 0.125f);
        }
    }
}

// ============================================================================
// K4 v3: gather aggregation + output GEMMs with weights amortized over the
// 4 node-groups.
// ============================================================================
__global__ __launch_bounds__(256) void k_agg(
    const int* __restrict__ send, const float* __restrict__ eattr,
    float* __restrict__ out)
{
    __shared__ __align__(16) float sms[4][128];
    __shared__ __align__(16) float sv0[4][192];
    __shared__ __align__(16) float sv1[4][192];
    __shared__ __align__(16) float sv2[4][192];

    const int t = threadIdx.x;
    const int g = t >> 6, c = t & 63;
    const int nb = blockIdx.x * 4;
    const int n = nb + g;
    const int e0 = g_off[n], e1 = g_off[n + 1];

    float as0 = 0.f, as1 = 0.f;
    ull   av0_01 = 0ull, av1_01 = 0ull, av2_01 = 0ull;
    float av0_2 = 0.f, av1_2 = 0.f, av2_2 = 0.f;

    for (int p = e0; p < e1; p++) {
        const int e = g_eord[p];
        const int s = __ldg(send + e);
        const float4 ea = __ldg((const float4*)eattr + e);
        const float sh0 = ea.x, s1x = ea.y, s1y = ea.z, s1z = ea.w;
        const float* tp = g_tpw + (size_t)e * 320 + c;
        const float w0 = tp[0], w1 = tp[64], w2 = tp[128], w3 = tp[192], w4 = tp[256];
        const float4 xq = __ldg(g_xq2 + (size_t)s * 64 + c);
        const float xs = xq.w;

        as0 = fmaf(w0 * xs, sh0, as0);
        const float dt = xq.x * s1x + xq.y * s1y + xq.z * s1z;
        as1 = fmaf(w3, dt, as1);

        const float t1 = w1 * xs;
        av0_01 = ff2(pk2(t1, t1), pk2(s1x, s1y), av0_01);
        av0_2  = fmaf(t1, s1z, av0_2);

        const float w2sh = w2 * sh0;
        av1_01 = ff2(pk2(xq.x, xq.y), pk2(w2sh, w2sh), av1_01);
        av1_2  = fmaf(w2sh, xq.z, av1_2);

        const float cx = xq.y * s1z - xq.z * s1y;
        const float cy = xq.z * s1x - xq.x * s1z;
        const float cz = xq.x * s1y - xq.y * s1x;
        av2_01 = ff2(pk2(cx, cy), pk2(w4, w4), av2_01);
        av2_2  = fmaf(w4, cz, av2_2);
    }

    const float INV  = 0.3535533905932738f;            // 1/sqrt(8)
    const float INV3 = INV * 0.5773502691896258f;
    const float INV2 = INV * 0.7071067811865476f;
    sms[g][c]      = as0 * INV;
    sms[g][64 + c] = as1 * INV3;
    {
        float a, b;
        upk2(av0_01, a, b);
        sv0[g][c] = a * INV;  sv1[g][c] = b * INV;  sv2[g][c] = av0_2 * INV;
        upk2(av1_01, a, b);
        sv0[g][64 + c] = a * INV;  sv1[g][64 + c] = b * INV;
        sv2[g][64 + c] = av1_2 * INV;
        upk2(av2_01, a, b);
        sv0[g][128 + c] = a * INV2;  sv1[g][128 + c] = b * INV2;
        sv2[g][128 + c] = av2_2 * INV2;
    }
    __syncthreads();

    if (t < 64) {
        const int d = t;
        ull os[4] = {0ull, 0ull, 0ull, 0ull};
#pragma unroll 4
        for (int kp = 0; kp < 64; kp++) {
            const ull w = __ldg(g_wms2 + kp * 64 + d);
#pragma unroll
            for (int q = 0; q < 4; q++)
                os[q] = ff2(((const ull*)sms[q])[kp], w, os[q]);
        }
#pragma unroll
        for (int q = 0; q < 4; q++)
            out[(size_t)(nb + q) * 64 + d] = fold2(os[q]) * 0.08838834764831845f;
    } else {
        const int u = t - 64;
        const int d = u & 63;
        const int comp = u >> 6;  // 0,1,2
        const float* pl = (comp == 0) ? &sv0[0][0]
                        : (comp == 1) ? &sv1[0][0] : &sv2[0][0];
        ull ov[4] = {0ull, 0ull, 0ull, 0ull};
#pragma unroll 4
        for (int kp = 0; kp < 96; kp++) {
            const ull w = __ldg(g_wmv2 + kp * 64 + d);
#pragma unroll
            for (int q = 0; q < 4; q++)
                ov[q] = ff2(((const ull*)(pl + q * 192))[kp], w, ov[q]);
        }
        const float S192 = 0.07216878364870323f;  // 1/sqrt(192)
#pragma unroll
        for (int q = 0; q < 4; q++)
            out[O_OUT_V + (size_t)(nb + q) * 192 + (size_t)d * 3 + comp] =
                fold2(ov[q]) * S192;
    }
}

// ============================================================================
// kernel_launch: prep -> fork{A: HMMA MLP, B: prepx/node/CSR} -> join -> agg
// ============================================================================
extern "C" void kernel_launch(void* const* d_in, const int* in_sizes, int n_in,
                              void* d_out, int out_size)
{
    const float* node_attrs = (const float*)d_in[0];
    const float* x_s        = (const float*)d_in[1];
    const float* x_v        = (const float*)d_in[2];
    const float* edge_attrs = (const float*)d_in[3];
    const float* edge_feats = (const float*)d_in[4];
    const int*   senders    = (const int*)d_in[5];
    const int*   receivers  = (const int*)d_in[6];
    const float* W_sc_s     = (const float*)d_in[7];
    const float* W_sc_v     = (const float*)d_in[8];
    const float* W_self_s   = (const float*)d_in[9];
    const float* W_self_v   = (const float*)d_in[10];
    const float* mlp_W0     = (const float*)d_in[11];
    const float* mlp_W1     = (const float*)d_in[12];
    const float* mlp_W2     = (const float*)d_in[13];
    const float* mlp_W3     = (const float*)d_in[14];
    const float* W_msg_s    = (const float*)d_in[15];
    const float* W_msg_v    = (const float*)d_in[16];
    float* out = (float*)d_out;

    static cudaStream_t s1 = nullptr;
    static cudaEvent_t evFork = nullptr, evJoin = nullptr;
    static bool init_done = false;
    if (!init_done) {
        cudaStreamCreateWithFlags(&s1, cudaStreamNonBlocking);
        cudaEventCreateWithFlags(&evFork, cudaEventDisableTiming);
        cudaEventCreateWithFlags(&evJoin, cudaEventDisableTiming);
        cudaFuncSetAttribute(k_node, cudaFuncAttributeMaxDynamicSharedMemorySize,
                             (int)((640 * 16 + 64 * 16) * 8));
        init_done = true;
    }

    const size_t node_smem = (size_t)(640 * 16) * 8 + (size_t)(64 * 16) * 8;

    // (1) weight prep (both branches depend on it)
    k_prep<<<160, 256, 0, 0>>>(W_sc_s, W_sc_v, W_self_s, W_self_v,
                               W_msg_s, W_msg_v, mlp_W1, mlp_W2, mlp_W3);
    cudaEventRecord(evFork, 0);
    cudaStreamWaitEvent(s1, evFork, 0);

    // branch B (s1): input pack+count -> node kernel -> CSR
    k_prepx<<<NN * 64 / 256, 256, 0, s1>>>(x_s, x_v, receivers);   // (2)
    k_node<<<dim3(128, 4), 256, node_smem, s1>>>(node_attrs, out); // (3)

    // branch A (default stream): HMMA MLP  — launch slot #4 (profiled)
    k_mlp<<<EE / 128, 128, 0, 0>>>(edge_feats, mlp_W0);            // (4)

    k_scan_a<<<32, 1024, 0, s1>>>();
    k_scan_b<<<1, 32, 0, s1>>>();
    k_scan_c<<<128, 256, 0, s1>>>();
    k_fill<<<EE / 256, 256, 0, s1>>>(receivers);
    k_sort<<<NN / 128, 128, 0, s1>>>();
    cudaEventRecord(evJoin, s1);

    cudaStreamWaitEvent(0, evJoin, 0);
    k_agg<<<NN / 4, 256, 0, 0>>>(senders, edge_attrs, out);
}

// round 15
// speedup vs baseline: 1.3073x; 1.1386x over previous
#include <cuda_runtime.h>
#include <cuda_bf16.h>
#include <cstdint>
#include <cstddef>

#define NN 32768
#define EE 262144

static const size_t O_OUT_V = (size_t)NN * 64;
static const size_t O_SC_S  = (size_t)NN * 256;
static const size_t O_SC_V  = (size_t)NN * 320;

typedef unsigned long long ull;

// ---------------- device scratch ----------------
__device__ float4 g_xq[(size_t)NN * 64];     // input pack: (xv0,xv1,xv2,xs)
__device__ float4 g_xq2[(size_t)NN * 64];    // self-mixed: (v0,v1,v2,s)
__device__ float  g_tpw[(size_t)EE * 320];
__device__ ull    g_wsv[640 * 64];           // packed (W_sc_s, W_sc_v)
__device__ float2 g_wself[64 * 64];          // packed (W_self_s, W_self_v)
__device__ ull    g_wms2[64 * 64];           // paired (Wms[2k][d], Wms[2k+1][d])
__device__ ull    g_wmv2[96 * 64];           // paired (Wmv[2k][d], Wmv[2k+1][d])
// bf16 hi/lo transposed MLP weights [n][k]
__device__ __align__(16) __nv_bfloat16 g_b1h[4096], g_b1l[4096];
__device__ __align__(16) __nv_bfloat16 g_b2h[4096], g_b2l[4096];
__device__ __align__(16) __nv_bfloat16 g_b3h[20480], g_b3l[20480];
__device__ int    g_cnt[NN];
__device__ int    g_off[NN + 1];
__device__ int    g_woff[NN];
__device__ int    g_eord[EE];
__device__ int    g_bsum[32];
__device__ int    g_bpre[32];

// ---------------- helpers ----------------
__device__ __forceinline__ ull pk2(float lo, float hi) {
    ull r; asm("mov.b64 %0, {%1, %2};" : "=l"(r) : "f"(lo), "f"(hi)); return r;
}
__device__ __forceinline__ void upk2(ull v, float& lo, float& hi) {
    asm("mov.b64 {%0, %1}, %2;" : "=f"(lo), "=f"(hi) : "l"(v));
}
__device__ __forceinline__ ull ff2(ull a, ull b, ull c) {
    ull d; asm("fma.rn.f32x2 %0, %1, %2, %3;" : "=l"(d) : "l"(a), "l"(b), "l"(c));
    return d;
}
__device__ __forceinline__ float fold2(ull v) {
    float lo, hi; upk2(v, lo, hi); return lo + hi;
}
__device__ __forceinline__ float silu_f(float x) {
    return x * __fdividef(1.0f, 1.0f + __expf(-x));
}
__device__ __forceinline__ void splitpack(float a, float b, uint32_t& hi, uint32_t& lo) {
    __nv_bfloat16 ah = __float2bfloat16(a), bh = __float2bfloat16(b);
    hi = ((uint32_t)__bfloat16_as_ushort(bh) << 16) | __bfloat16_as_ushort(ah);
    __nv_bfloat16 al = __float2bfloat16(a - __bfloat162float(ah));
    __nv_bfloat16 bl = __float2bfloat16(b - __bfloat162float(bh));
    lo = ((uint32_t)__bfloat16_as_ushort(bl) << 16) | __bfloat16_as_ushort(al);
}
__device__ __forceinline__ void mma_bf16(float d[4], const uint32_t a[4],
                                         const uint32_t b0, const uint32_t b1) {
    asm volatile(
        "mma.sync.aligned.m16n8k16.row.col.f32.bf16.bf16.f32 "
        "{%0,%1,%2,%3}, {%4,%5,%6,%7}, {%8,%9}, {%0,%1,%2,%3};"
        : "+f"(d[0]), "+f"(d[1]), "+f"(d[2]), "+f"(d[3])
        : "r"(a[0]), "r"(a[1]), "r"(a[2]), "r"(a[3]), "r"(b0), "r"(b1));
}

// ============================================================================
// K_prep: pack weights (node, self, output GEMM) + bf16 hi/lo transposed MLP
// ============================================================================
__global__ void k_prep(const float* __restrict__ Wscs, const float* __restrict__ Wscv,
                       const float* __restrict__ Wss,  const float* __restrict__ Wsv,
                       const float* __restrict__ Wms,  const float* __restrict__ Wmv,
                       const float* __restrict__ W1,   const float* __restrict__ W2,
                       const float* __restrict__ W3) {
    const int i = blockIdx.x * 256 + threadIdx.x;
    if (i < 640 * 64) g_wsv[i] = pk2(Wscs[i], Wscv[i]);
    if (i < 64 * 64)  g_wself[i] = make_float2(Wss[i], Wsv[i]);
    if (i < 64 * 64) {
        const int kp = i >> 6, d = i & 63;
        g_wms2[i] = pk2(Wms[(2 * kp) * 64 + d], Wms[(2 * kp + 1) * 64 + d]);
    }
    if (i < 96 * 64) {
        const int kp = i >> 6, d = i & 63;
        g_wmv2[i] = pk2(Wmv[(2 * kp) * 64 + d], Wmv[(2 * kp + 1) * 64 + d]);
    }
    if (i < 4096) {
        const int k = i >> 6, n = i & 63;
        float w = W1[i];
        __nv_bfloat16 h = __float2bfloat16(w);
        g_b1h[n * 64 + k] = h;
        g_b1l[n * 64 + k] = __float2bfloat16(w - __bfloat162float(h));
        w = W2[i];
        h = __float2bfloat16(w);
        g_b2h[n * 64 + k] = h;
        g_b2l[n * 64 + k] = __float2bfloat16(w - __bfloat162float(h));
    }
    if (i < 20480) {
        const int k = i / 320, n = i % 320;
        const float w = W3[i];
        const __nv_bfloat16 h = __float2bfloat16(w);
        g_b3h[n * 64 + k] = h;
        g_b3l[n * 64 + k] = __float2bfloat16(w - __bfloat162float(h));
    }
    if (i < NN) g_cnt[i] = 0;
}

// K_prepx: pack (x_v, x_s) into float4; fused receiver histogram
__global__ void k_prepx(const float* __restrict__ xs_in,
                        const float* __restrict__ xv_in,
                        const int* __restrict__ recv) {
    const size_t i = (size_t)blockIdx.x * 256 + threadIdx.x;  // over N*C
    const float xs = xs_in[i];
    const float* p = xv_in + i * 3;
    g_xq[i] = make_float4(p[0], p[1], p[2], xs);
    if (i < EE) atomicAdd(&g_cnt[recv[i]], 1);
}

// ============================================================================
// K2 v9: HMMA (mma.sync bf16 hi+lo split) edge MLP, register-chained layers.
// 128 edges/block, 128 threads. W1/W2 in smem (pitch 72); W3 chunks STAGED
// into the (dead) W1 buffers per chunk with coalesced LDG.128 -> LDS.
// ============================================================================
#define WPITCH 72  // bf16 row pitch: 144 B -> 36-word stride (conflict-free)

__global__ __launch_bounds__(128, 3) void k_mlp(
    const float* __restrict__ feats, const float* __restrict__ W0)
{
    __shared__ float sW0[512];
    __shared__ __align__(16) __nv_bfloat16 sW1h[64 * WPITCH], sW1l[64 * WPITCH];
    __shared__ __align__(16) __nv_bfloat16 sW2h[64 * WPITCH], sW2l[64 * WPITCH];
    __shared__ float sF[1024];

    const int t = threadIdx.x;
    const int warp = t >> 5, lane = t & 31;
    const int t4 = lane & 3, gid = lane >> 2;

    for (int i = t; i < 512; i += 128) sW0[i] = W0[i];
    for (int i = t; i < 4096; i += 128) {
        const int n = i >> 6, k = i & 63;
        sW1h[n * WPITCH + k] = g_b1h[i];
        sW1l[n * WPITCH + k] = g_b1l[i];
        sW2h[n * WPITCH + k] = g_b2h[i];
        sW2l[n * WPITCH + k] = g_b2l[i];
    }
    const size_t fbase = (size_t)blockIdx.x * 1024;
    for (int i = t; i < 1024; i += 128) sF[i] = feats[fbase + i];  // [e][k]
    __syncthreads();

    // -------- layer 0: scalar K=8, results written directly as A fragments
    uint32_t Ah[2][4][4], Al[2][4][4];   // [mtile][ktile][reg]
#pragma unroll
    for (int mt = 0; mt < 2; mt++) {
#pragma unroll
        for (int row = 0; row < 2; row++) {
            const int el = warp * 32 + mt * 16 + row * 8 + gid;
            const float* f = sF + el * 8;
            float fr[8];
#pragma unroll
            for (int k = 0; k < 8; k++) fr[k] = f[k];
#pragma unroll
            for (int kt = 0; kt < 4; kt++) {
#pragma unroll
                for (int b = 0; b < 2; b++) {
                    const int c0 = kt * 16 + b * 8 + t4 * 2;
                    float h0 = 0.f, h1 = 0.f;
#pragma unroll
                    for (int k = 0; k < 8; k++) {
                        h0 = fmaf(fr[k], sW0[k * 64 + c0], h0);
                        h1 = fmaf(fr[k], sW0[k * 64 + c0 + 1], h1);
                    }
                    h0 = silu_f(h0 * 0.3535533905932738f);
                    h1 = silu_f(h1 * 0.3535533905932738f);
                    splitpack(h0, h1, Ah[mt][kt][row + 2 * b],
                                       Al[mt][kt][row + 2 * b]);
                }
            }
        }
    }

    float D[2][8][4];

    // -------- layers 1 and 2 (64->64, silu(x/8)), weights from smem
#pragma unroll 1
    for (int L = 0; L < 2; L++) {
        const __nv_bfloat16* Wh = L ? sW2h : sW1h;
        const __nv_bfloat16* Wl = L ? sW2l : sW1l;
#pragma unroll
        for (int mt = 0; mt < 2; mt++)
#pragma unroll
            for (int nt = 0; nt < 8; nt++)
#pragma unroll
                for (int q = 0; q < 4; q++) D[mt][nt][q] = 0.f;

#pragma unroll
        for (int nt = 0; nt < 8; nt++) {
            const uint32_t* ph = (const uint32_t*)(Wh + (nt * 8 + gid) * WPITCH);
            const uint32_t* pl = (const uint32_t*)(Wl + (nt * 8 + gid) * WPITCH);
            uint32_t bh[4][2], bl[4][2];
#pragma unroll
            for (int kt = 0; kt < 4; kt++) {
                bh[kt][0] = ph[kt * 8 + t4];  bh[kt][1] = ph[kt * 8 + t4 + 4];
                bl[kt][0] = pl[kt * 8 + t4];  bl[kt][1] = pl[kt * 8 + t4 + 4];
            }
#pragma unroll
            for (int mt = 0; mt < 2; mt++)
#pragma unroll
                for (int kt = 0; kt < 4; kt++) {
                    mma_bf16(D[mt][nt], Ah[mt][kt], bh[kt][0], bh[kt][1]);
                    mma_bf16(D[mt][nt], Ah[mt][kt], bl[kt][0], bl[kt][1]);
                    mma_bf16(D[mt][nt], Al[mt][kt], bh[kt][0], bh[kt][1]);
                }
        }

        // epilogue: silu + re-split into next A fragments (register chaining)
#pragma unroll
        for (int mt = 0; mt < 2; mt++)
#pragma unroll
            for (int kt = 0; kt < 4; kt++) {
                const float* da = D[mt][2 * kt];
                const float* db = D[mt][2 * kt + 1];
                float v0 = silu_f(da[0] * 0.125f), v1 = silu_f(da[1] * 0.125f);
                splitpack(v0, v1, Ah[mt][kt][0], Al[mt][kt][0]);
                v0 = silu_f(da[2] * 0.125f); v1 = silu_f(da[3] * 0.125f);
                splitpack(v0, v1, Ah[mt][kt][1], Al[mt][kt][1]);
                v0 = silu_f(db[0] * 0.125f); v1 = silu_f(db[1] * 0.125f);
                splitpack(v0, v1, Ah[mt][kt][2], Al[mt][kt][2]);
                v0 = silu_f(db[2] * 0.125f); v1 = silu_f(db[3] * 0.125f);
                splitpack(v0, v1, Ah[mt][kt][3], Al[mt][kt][3]);
            }
    }

    // -------- layer 3 (64 -> 320, x/8), 5 chunks of 64
    // W3 chunk staged into sW1h/sW1l (dead after layer 1) via coalesced LDG.128
    const int eb = blockIdx.x * 128 + warp * 32;
#pragma unroll 1
    for (int ch = 0; ch < 5; ch++) {
        __syncthreads();   // prior chunk's LDS reads complete
        {
            const uint4* p3h = (const uint4*)g_b3h + ch * 512;
            const uint4* p3l = (const uint4*)g_b3l + ch * 512;
#pragma unroll
            for (int it = 0; it < 4; it++) {
                const int i = t + it * 128;          // 0..511
                const int n = i >> 3, q = i & 7;     // row n, 16B-group q
                const uint32_t boff = n * (WPITCH * 2) + q * 16;
                *(uint4*)((char*)sW1h + boff) = __ldg(p3h + i);
                *(uint4*)((char*)sW1l + boff) = __ldg(p3l + i);
            }
        }
        __syncthreads();

#pragma unroll
        for (int mt = 0; mt < 2; mt++)
#pragma unroll
            for (int nt = 0; nt < 8; nt++)
#pragma unroll
                for (int q = 0; q < 4; q++) D[mt][nt][q] = 0.f;

#pragma unroll
        for (int nt = 0; nt < 8; nt++) {
            const uint32_t* ph = (const uint32_t*)(sW1h + (nt * 8 + gid) * WPITCH);
            const uint32_t* pl = (const uint32_t*)(sW1l + (nt * 8 + gid) * WPITCH);
            uint32_t bh[4][2], bl[4][2];
#pragma unroll
            for (int kt = 0; kt < 4; kt++) {
                bh[kt][0] = ph[kt * 8 + t4];  bh[kt][1] = ph[kt * 8 + t4 + 4];
                bl[kt][0] = pl[kt * 8 + t4];  bl[kt][1] = pl[kt * 8 + t4 + 4];
            }
#pragma unroll
            for (int mt = 0; mt < 2; mt++)
#pragma unroll
                for (int kt = 0; kt < 4; kt++) {
                    mma_bf16(D[mt][nt], Ah[mt][kt], bh[kt][0], bh[kt][1]);
                    mma_bf16(D[mt][nt], Ah[mt][kt], bl[kt][0], bl[kt][1]);
                    mma_bf16(D[mt][nt], Al[mt][kt], bh[kt][0], bh[kt][1]);
                }
        }

        // store: d0,d1 -> row gid; d2,d3 -> row gid+8 (x/8, no silu)
#pragma unroll
        for (int mt = 0; mt < 2; mt++) {
            const int e0 = eb + mt * 16 + gid;
#pragma unroll
            for (int nt = 0; nt < 8; nt++) {
                const int col = ch * 64 + nt * 8 + t4 * 2;
                const float* d = D[mt][nt];
                *(float2*)(g_tpw + (size_t)e0 * 320 + col) =
                    make_float2(d[0] * 0.125f, d[1] * 0.125f);
                *(float2*)(g_tpw + (size_t)(e0 + 8) * 320 + col) =
                    make_float2(d[2] * 0.125f, d[3] * 0.125f);
            }
        }
    }
}

// ============================================================================
// CSR build: hierarchical scan -> fill -> sort (count fused into k_prepx)
// ============================================================================
__global__ void k_scan_a() {      // grid 32, block 1024
    __shared__ int ss[1024];
    const int t = threadIdx.x;
    const int i = blockIdx.x * 1024 + t;
    const int v = g_cnt[i];
    ss[t] = v;
    __syncthreads();
    for (int dd = 1; dd < 1024; dd <<= 1) {
        const int u = (t >= dd) ? ss[t - dd] : 0;
        __syncthreads();
        ss[t] += u;
        __syncthreads();
    }
    g_off[i] = ss[t] - v;
    g_woff[i] = 0;
    if (t == 1023) g_bsum[blockIdx.x] = ss[t];
}
__global__ void k_scan_b() {      // 1 block, 32 threads
    const int t = threadIdx.x;
    const int orig = g_bsum[t];
    int v = orig;
    for (int dd = 1; dd < 32; dd <<= 1) {
        const int u = __shfl_up_sync(0xffffffffu, v, dd);
        if (t >= dd) v += u;
    }
    g_bpre[t] = v - orig;
    if (t == 31) g_off[NN] = v;
}
__global__ void k_scan_c() {      // grid 128 x 256
    const int i = blockIdx.x * 256 + threadIdx.x;
    g_off[i] += g_bpre[i >> 10];
}
__global__ void k_fill(const int* __restrict__ recv) {
    const int e = blockIdx.x * blockDim.x + threadIdx.x;
    if (e < EE) {
        const int r = recv[e];
        const int p = atomicAdd(&g_woff[r], 1);
        g_eord[g_off[r] + p] = e;
    }
}
__global__ void k_sort() {
    const int n = blockIdx.x * blockDim.x + threadIdx.x;
    if (n >= NN) return;
    const int s = g_off[n], e = g_off[n + 1];
    for (int i = s + 1; i < e; i++) {
        const int v = g_eord[i];
        int j = i - 1;
        while (j >= s && g_eord[j] > v) { g_eord[j + 1] = g_eord[j]; j--; }
        g_eord[j + 1] = v;
    }
}

// ============================================================================
// K1 (R10): per-node sc_s/sc_v + self-mix, weights smem-stationary,
// d-quartered. grid (128, 4) x 256 threads; dyn smem 90112 B
// ============================================================================
__global__ __launch_bounds__(256, 2) void k_node(
    const float* __restrict__ attr, float* __restrict__ out)
{
    extern __shared__ ull dynsm[];
    ull*    swsv   = dynsm;                        // [c*160 + a*16 + d]
    float2* swself = (float2*)(dynsm + 640 * 16);  // [c*16 + d]

    const int t = threadIdx.x;
    const int dq = blockIdx.y;
    const int dd = dq * 16;

    for (int i = t; i < 640 * 16; i += 256) {
        const int ca = i >> 4, d_ = i & 15;
        swsv[i] = g_wsv[ca * 64 + dd + d_];
    }
    for (int i = t; i < 64 * 16; i += 256) {
        const int c = i >> 4, d_ = i & 15;
        swself[i] = g_wself[c * 64 + dd + d_];
    }
    __syncthreads();

    const int d = t & 15, grp = t >> 4;
    const int nbase = blockIdx.x * 256 + grp * 16;
    const int D_ = dd + d;
    const float S640 = 0.039528470752104741f;  // 1/sqrt(640)

    for (int pass = 0; pass < 8; pass++) {
        const int nA = nbase + pass * 2;
        const int nB = nA + 1;

        ull aPA[10], aPB[10];
#pragma unroll
        for (int a = 0; a < 10; a++) {
            const float vA = __ldg(attr + (size_t)nA * 10 + a);
            const float vB = __ldg(attr + (size_t)nB * 10 + a);
            aPA[a] = pk2(vA, vA);
            aPB[a] = pk2(vB, vB);
        }

        float accS[2]  = {0.f, 0.f}, accS2[2] = {0.f, 0.f};
        float aV2[2]   = {0.f, 0.f}, aV2s[2]  = {0.f, 0.f};
        ull   aV01[2]  = {0ull, 0ull}, aV01s[2] = {0ull, 0ull};

        const float4* xqA = g_xq + (size_t)nA * 64;
        const float4* xqB = g_xq + (size_t)nB * 64;

#pragma unroll 2
        for (int c = 0; c < 64; c++) {
            const float4 xA = __ldg(xqA + c);
            const float4 xB = __ldg(xqB + c);
            const float2 wsf = swself[c * 16 + d];
            const ull wvd = pk2(wsf.y, wsf.y);

            accS2[0]  = fmaf(xA.w, wsf.x, accS2[0]);
            aV01s[0]  = ff2(pk2(xA.x, xA.y), wvd, aV01s[0]);
            aV2s[0]   = fmaf(xA.z, wsf.y, aV2s[0]);
            accS2[1]  = fmaf(xB.w, wsf.x, accS2[1]);
            aV01s[1]  = ff2(pk2(xB.x, xB.y), wvd, aV01s[1]);
            aV2s[1]   = fmaf(xB.z, wsf.y, aV2s[1]);

            ull mA = 0ull, mB = 0ull;
            const ull* wp = swsv + c * 160 + d;
#pragma unroll
            for (int a = 0; a < 10; a++) {
                const ull w = wp[a * 16];
                mA = ff2(aPA[a], w, mA);
                mB = ff2(aPB[a], w, mB);
            }
            float MsA, MvA, MsB, MvB;
            upk2(mA, MsA, MvA);
            upk2(mB, MsB, MvB);

            accS[0] = fmaf(xA.w, MsA, accS[0]);
            aV01[0] = ff2(pk2(xA.x, xA.y), pk2(MvA, MvA), aV01[0]);
            aV2[0]  = fmaf(xA.z, MvA, aV2[0]);
            accS[1] = fmaf(xB.w, MsB, accS[1]);
            aV01[1] = ff2(pk2(xB.x, xB.y), pk2(MvB, MvB), aV01[1]);
            aV2[1]  = fmaf(xB.z, MvB, aV2[1]);
        }

#pragma unroll
        for (int j = 0; j < 2; j++) {
            const int n = nA + j;
            out[O_SC_S + (size_t)n * 64 + D_] = accS[j] * S640;
            float v0, v1; upk2(aV01[j], v0, v1);
            const size_t vb = O_SC_V + (size_t)n * 192 + (size_t)D_ * 3;
            out[vb]     = v0 * S640;
            out[vb + 1] = v1 * S640;
            out[vb + 2] = aV2[j] * S640;
            float s0, s1; upk2(aV01s[j], s0, s1);
            g_xq2[(size_t)n * 64 + D_] =
                make_float4(s0 * 0.125f, s1 * 0.125f, aV2s[j] * 0.125f,
                            accS2[j] * 0.125f);
        }
    }
}

// ============================================================================
// K4 v3: gather aggregation + output GEMMs with weights amortized over the
// 4 node-groups.
// ============================================================================
__global__ __launch_bounds__(256) void k_agg(
    const int* __restrict__ send, const float* __restrict__ eattr,
    float* __restrict__ out)
{
    __shared__ __align__(16) float sms[4][128];
    __shared__ __align__(16) float sv0[4][192];
    __shared__ __align__(16) float sv1[4][192];
    __shared__ __align__(16) float sv2[4][192];

    const int t = threadIdx.x;
    const int g = t >> 6, c = t & 63;
    const int nb = blockIdx.x * 4;
    const int n = nb + g;
    const int e0 = g_off[n], e1 = g_off[n + 1];

    float as0 = 0.f, as1 = 0.f;
    ull   av0_01 = 0ull, av1_01 = 0ull, av2_01 = 0ull;
    float av0_2 = 0.f, av1_2 = 0.f, av2_2 = 0.f;

    for (int p = e0; p < e1; p++) {
        const int e = g_eord[p];
        const int s = __ldg(send + e);
        const float4 ea = __ldg((const float4*)eattr + e);
        const float sh0 = ea.x, s1x = ea.y, s1y = ea.z, s1z = ea.w;
        const float* tp = g_tpw + (size_t)e * 320 + c;
        const float w0 = tp[0], w1 = tp[64], w2 = tp[128], w3 = tp[192], w4 = tp[256];
        const float4 xq = __ldg(g_xq2 + (size_t)s * 64 + c);
        const float xs = xq.w;

        as0 = fmaf(w0 * xs, sh0, as0);
        const float dt = xq.x * s1x + xq.y * s1y + xq.z * s1z;
        as1 = fmaf(w3, dt, as1);

        const float t1 = w1 * xs;
        av0_01 = ff2(pk2(t1, t1), pk2(s1x, s1y), av0_01);
        av0_2  = fmaf(t1, s1z, av0_2);

        const float w2sh = w2 * sh0;
        av1_01 = ff2(pk2(xq.x, xq.y), pk2(w2sh, w2sh), av1_01);
        av1_2  = fmaf(w2sh, xq.z, av1_2);

        const float cx = xq.y * s1z - xq.z * s1y;
        const float cy = xq.z * s1x - xq.x * s1z;
        const float cz = xq.x * s1y - xq.y * s1x;
        av2_01 = ff2(pk2(cx, cy), pk2(w4, w4), av2_01);
        av2_2  = fmaf(w4, cz, av2_2);
    }

    const float INV  = 0.3535533905932738f;            // 1/sqrt(8)
    const float INV3 = INV * 0.5773502691896258f;
    const float INV2 = INV * 0.7071067811865476f;
    sms[g][c]      = as0 * INV;
    sms[g][64 + c] = as1 * INV3;
    {
        float a, b;
        upk2(av0_01, a, b);
        sv0[g][c] = a * INV;  sv1[g][c] = b * INV;  sv2[g][c] = av0_2 * INV;
        upk2(av1_01, a, b);
        sv0[g][64 + c] = a * INV;  sv1[g][64 + c] = b * INV;
        sv2[g][64 + c] = av1_2 * INV;
        upk2(av2_01, a, b);
        sv0[g][128 + c] = a * INV2;  sv1[g][128 + c] = b * INV2;
        sv2[g][128 + c] = av2_2 * INV2;
    }
    __syncthreads();

    if (t < 64) {
        const int d = t;
        ull os[4] = {0ull, 0ull, 0ull, 0ull};
#pragma unroll 4
        for (int kp = 0; kp < 64; kp++) {
            const ull w = __ldg(g_wms2 + kp * 64 + d);
#pragma unroll
            for (int q = 0; q < 4; q++)
                os[q] = ff2(((const ull*)sms[q])[kp], w, os[q]);
        }
#pragma unroll
        for (int q = 0; q < 4; q++)
            out[(size_t)(nb + q) * 64 + d] = fold2(os[q]) * 0.08838834764831845f;
    } else {
        const int u = t - 64;
        const int d = u & 63;
        const int comp = u >> 6;  // 0,1,2
        const float* pl = (comp == 0) ? &sv0[0][0]
                        : (comp == 1) ? &sv1[0][0] : &sv2[0][0];
        ull ov[4] = {0ull, 0ull, 0ull, 0ull};
#pragma unroll 4
        for (int kp = 0; kp < 96; kp++) {
            const ull w = __ldg(g_wmv2 + kp * 64 + d);
#pragma unroll
            for (int q = 0; q < 4; q++)
                ov[q] = ff2(((const ull*)(pl + q * 192))[kp], w, ov[q]);
        }
        const float S192 = 0.07216878364870323f;  // 1/sqrt(192)
#pragma unroll
        for (int q = 0; q < 4; q++)
            out[O_OUT_V + (size_t)(nb + q) * 192 + (size_t)d * 3 + comp] =
                fold2(ov[q]) * S192;
    }
}

// ============================================================================
// kernel_launch: prep -> fork{A: HMMA MLP, B: prepx/node/CSR} -> join -> agg
// ============================================================================
extern "C" void kernel_launch(void* const* d_in, const int* in_sizes, int n_in,
                              void* d_out, int out_size)
{
    const float* node_attrs = (const float*)d_in[0];
    const float* x_s        = (const float*)d_in[1];
    const float* x_v        = (const float*)d_in[2];
    const float* edge_attrs = (const float*)d_in[3];
    const float* edge_feats = (const float*)d_in[4];
    const int*   senders    = (const int*)d_in[5];
    const int*   receivers  = (const int*)d_in[6];
    const float* W_sc_s     = (const float*)d_in[7];
    const float* W_sc_v     = (const float*)d_in[8];
    const float* W_self_s   = (const float*)d_in[9];
    const float* W_self_v   = (const float*)d_in[10];
    const float* mlp_W0     = (const float*)d_in[11];
    const float* mlp_W1     = (const float*)d_in[12];
    const float* mlp_W2     = (const float*)d_in[13];
    const float* mlp_W3     = (const float*)d_in[14];
    const float* W_msg_s    = (const float*)d_in[15];
    const float* W_msg_v    = (const float*)d_in[16];
    float* out = (float*)d_out;

    static cudaStream_t s1 = nullptr;
    static cudaEvent_t evFork = nullptr, evJoin = nullptr;
    static bool init_done = false;
    if (!init_done) {
        cudaStreamCreateWithFlags(&s1, cudaStreamNonBlocking);
        cudaEventCreateWithFlags(&evFork, cudaEventDisableTiming);
        cudaEventCreateWithFlags(&evJoin, cudaEventDisableTiming);
        cudaFuncSetAttribute(k_node, cudaFuncAttributeMaxDynamicSharedMemorySize,
                             (int)((640 * 16 + 64 * 16) * 8));
        init_done = true;
    }

    const size_t node_smem = (size_t)(640 * 16) * 8 + (size_t)(64 * 16) * 8;

    // (1) weight prep (both branches depend on it)
    k_prep<<<160, 256, 0, 0>>>(W_sc_s, W_sc_v, W_self_s, W_self_v,
                               W_msg_s, W_msg_v, mlp_W1, mlp_W2, mlp_W3);
    cudaEventRecord(evFork, 0);
    cudaStreamWaitEvent(s1, evFork, 0);

    // branch B (s1): input pack+count -> node kernel -> CSR
    k_prepx<<<NN * 64 / 256, 256, 0, s1>>>(x_s, x_v, receivers);   // (2)
    k_node<<<dim3(128, 4), 256, node_smem, s1>>>(node_attrs, out); // (3)

    // branch A (default stream): HMMA MLP  — launch slot #4 (profiled)
    k_mlp<<<EE / 128, 128, 0, 0>>>(edge_feats, mlp_W0);            // (4)

    k_scan_a<<<32, 1024, 0, s1>>>();
    k_scan_b<<<1, 32, 0, s1>>>();
    k_scan_c<<<128, 256, 0, s1>>>();
    k_fill<<<EE / 256, 256, 0, s1>>>(receivers);
    k_sort<<<NN / 128, 128, 0, s1>>>();
    cudaEventRecord(evJoin, s1);

    cudaStreamWaitEvent(0, evJoin, 0);
    k_agg<<<NN / 4, 256, 0, 0>>>(senders, edge_attrs, out);
}

// round 16
// speedup vs baseline: 1.3946x; 1.0667x over previous
#include <cuda_runtime.h>
#include <cuda_bf16.h>
#include <cstdint>
#include <cstddef>

#define NN 32768
#define EE 262144

static const size_t O_OUT_V = (size_t)NN * 64;
static const size_t O_SC_S  = (size_t)NN * 256;
static const size_t O_SC_V  = (size_t)NN * 320;

typedef unsigned long long ull;

// ---------------- device scratch ----------------
__device__ float4 g_xq[(size_t)NN * 64];     // input pack: (xv0,xv1,xv2,xs)
__device__ float4 g_xq2[(size_t)NN * 64];    // self-mixed: (v0,v1,v2,s)
__device__ float  g_tpw[(size_t)EE * 320];
__device__ ull    g_wsv[640 * 64];           // packed (W_sc_s, W_sc_v)
__device__ float2 g_wself[64 * 64];          // packed (W_self_s, W_self_v)
__device__ ull    g_wms2[64 * 64];           // paired (Wms[2k][d], Wms[2k+1][d])
__device__ ull    g_wmv2[96 * 64];           // paired (Wmv[2k][d], Wmv[2k+1][d])
// bf16 hi/lo transposed MLP weights [n][k]
__device__ __align__(16) __nv_bfloat16 g_b1h[4096], g_b1l[4096];
__device__ __align__(16) __nv_bfloat16 g_b2h[4096], g_b2l[4096];
__device__ __align__(16) __nv_bfloat16 g_b3h[20480], g_b3l[20480];
__device__ int    g_cnt[NN];
__device__ int    g_off[NN + 1];
__device__ int    g_woff[NN];
__device__ int    g_eord[EE];
__device__ int    g_bsum[32];
__device__ int    g_bpre[32];

// ---------------- helpers ----------------
__device__ __forceinline__ ull pk2(float lo, float hi) {
    ull r; asm("mov.b64 %0, {%1, %2};" : "=l"(r) : "f"(lo), "f"(hi)); return r;
}
__device__ __forceinline__ void upk2(ull v, float& lo, float& hi) {
    asm("mov.b64 {%0, %1}, %2;" : "=f"(lo), "=f"(hi) : "l"(v));
}
__device__ __forceinline__ ull ff2(ull a, ull b, ull c) {
    ull d; asm("fma.rn.f32x2 %0, %1, %2, %3;" : "=l"(d) : "l"(a), "l"(b), "l"(c));
    return d;
}
__device__ __forceinline__ float fold2(ull v) {
    float lo, hi; upk2(v, lo, hi); return lo + hi;
}
__device__ __forceinline__ float silu_f(float x) {
    return x * __fdividef(1.0f, 1.0f + __expf(-x));
}
__device__ __forceinline__ void splitpack(float a, float b, uint32_t& hi, uint32_t& lo) {
    __nv_bfloat16 ah = __float2bfloat16(a), bh = __float2bfloat16(b);
    hi = ((uint32_t)__bfloat16_as_ushort(bh) << 16) | __bfloat16_as_ushort(ah);
    __nv_bfloat16 al = __float2bfloat16(a - __bfloat162float(ah));
    __nv_bfloat16 bl = __float2bfloat16(b - __bfloat162float(bh));
    lo = ((uint32_t)__bfloat16_as_ushort(bl) << 16) | __bfloat16_as_ushort(al);
}
__device__ __forceinline__ void mma_bf16(float d[4], const uint32_t a[4],
                                         const uint32_t b0, const uint32_t b1) {
    asm volatile(
        "mma.sync.aligned.m16n8k16.row.col.f32.bf16.bf16.f32 "
        "{%0,%1,%2,%3}, {%4,%5,%6,%7}, {%8,%9}, {%0,%1,%2,%3};"
        : "+f"(d[0]), "+f"(d[1]), "+f"(d[2]), "+f"(d[3])
        : "r"(a[0]), "r"(a[1]), "r"(a[2]), "r"(a[3]), "r"(b0), "r"(b1));
}

// ============================================================================
// K_prep: pack weights (node, self, output GEMM) + bf16 hi/lo transposed MLP
// ============================================================================
__global__ void k_prep(const float* __restrict__ Wscs, const float* __restrict__ Wscv,
                       const float* __restrict__ Wss,  const float* __restrict__ Wsv,
                       const float* __restrict__ Wms,  const float* __restrict__ Wmv,
                       const float* __restrict__ W1,   const float* __restrict__ W2,
                       const float* __restrict__ W3) {
    const int i = blockIdx.x * 256 + threadIdx.x;
    if (i < 640 * 64) g_wsv[i] = pk2(Wscs[i], Wscv[i]);
    if (i < 64 * 64)  g_wself[i] = make_float2(Wss[i], Wsv[i]);
    if (i < 64 * 64) {
        const int kp = i >> 6, d = i & 63;
        g_wms2[i] = pk2(Wms[(2 * kp) * 64 + d], Wms[(2 * kp + 1) * 64 + d]);
    }
    if (i < 96 * 64) {
        const int kp = i >> 6, d = i & 63;
        g_wmv2[i] = pk2(Wmv[(2 * kp) * 64 + d], Wmv[(2 * kp + 1) * 64 + d]);
    }
    if (i < 4096) {
        const int k = i >> 6, n = i & 63;
        float w = W1[i];
        __nv_bfloat16 h = __float2bfloat16(w);
        g_b1h[n * 64 + k] = h;
        g_b1l[n * 64 + k] = __float2bfloat16(w - __bfloat162float(h));
        w = W2[i];
        h = __float2bfloat16(w);
        g_b2h[n * 64 + k] = h;
        g_b2l[n * 64 + k] = __float2bfloat16(w - __bfloat162float(h));
    }
    if (i < 20480) {
        const int k = i / 320, n = i % 320;
        const float w = W3[i];
        const __nv_bfloat16 h = __float2bfloat16(w);
        g_b3h[n * 64 + k] = h;
        g_b3l[n * 64 + k] = __float2bfloat16(w - __bfloat162float(h));
    }
    if (i < NN) g_cnt[i] = 0;
}

// K_prepx: pack (x_v, x_s) into float4; fused receiver histogram
__global__ void k_prepx(const float* __restrict__ xs_in,
                        const float* __restrict__ xv_in,
                        const int* __restrict__ recv) {
    const size_t i = (size_t)blockIdx.x * 256 + threadIdx.x;  // over N*C
    const float xs = xs_in[i];
    const float* p = xv_in + i * 3;
    g_xq[i] = make_float4(p[0], p[1], p[2], xs);
    if (i < EE) atomicAdd(&g_cnt[recv[i]], 1);
}

// ============================================================================
// K_self: self-mix only -> g_xq2 (what k_agg depends on).
// grid NN/4, 256 threads; 4 nodes/block, thread = (g, d)
// ============================================================================
__global__ __launch_bounds__(256) void k_self()
{
    __shared__ float4 sx[4 * 64];
    const int t = threadIdx.x;
    const int n0 = blockIdx.x * 4;
    sx[t] = g_xq[(size_t)n0 * 64 + t];
    __syncthreads();

    const int g = t >> 6, d = t & 63;
    float s = 0.f, v2 = 0.f;
    ull v01 = 0ull;
#pragma unroll 4
    for (int c = 0; c < 64; c++) {
        const float4 x = sx[g * 64 + c];            // (xv0, xv1, xv2, xs)
        const float2 w = __ldg(&g_wself[c * 64 + d]); // (ws, wv)
        s  = fmaf(x.w, w.x, s);
        v01 = ff2(pk2(x.x, x.y), pk2(w.y, w.y), v01);
        v2 = fmaf(x.z, w.y, v2);
    }
    float v0, v1; upk2(v01, v0, v1);
    g_xq2[(size_t)(n0 + g) * 64 + d] =
        make_float4(v0 * 0.125f, v1 * 0.125f, v2 * 0.125f, s * 0.125f);
}

// ============================================================================
// K_sc: attr-mixed sc_s / sc_v only (off the critical path).
// grid (128, 4) x 256 threads; dyn smem 81920 B; reg-capped for co-residency.
// ============================================================================
__global__ __launch_bounds__(256, 3) void k_sc(
    const float* __restrict__ attr, float* __restrict__ out)
{
    extern __shared__ ull dynsm[];
    ull* swsv = dynsm;                             // [c*160 + a*16 + d]

    const int t = threadIdx.x;
    const int dq = blockIdx.y;
    const int dd = dq * 16;

    for (int i = t; i < 640 * 16; i += 256) {
        const int ca = i >> 4, d_ = i & 15;
        swsv[i] = g_wsv[ca * 64 + dd + d_];
    }
    __syncthreads();

    const int d = t & 15, grp = t >> 4;
    const int nbase = blockIdx.x * 256 + grp * 16;
    const int D_ = dd + d;
    const float S640 = 0.039528470752104741f;  // 1/sqrt(640)

    for (int pass = 0; pass < 8; pass++) {
        const int nA = nbase + pass * 2;
        const int nB = nA + 1;

        ull aPA[10], aPB[10];
#pragma unroll
        for (int a = 0; a < 10; a++) {
            const float vA = __ldg(attr + (size_t)nA * 10 + a);
            const float vB = __ldg(attr + (size_t)nB * 10 + a);
            aPA[a] = pk2(vA, vA);
            aPB[a] = pk2(vB, vB);
        }

        float accS[2] = {0.f, 0.f};
        float aV2[2]  = {0.f, 0.f};
        ull   aV01[2] = {0ull, 0ull};

        const float4* xqA = g_xq + (size_t)nA * 64;
        const float4* xqB = g_xq + (size_t)nB * 64;

#pragma unroll 2
        for (int c = 0; c < 64; c++) {
            const float4 xA = __ldg(xqA + c);
            const float4 xB = __ldg(xqB + c);

            ull mA = 0ull, mB = 0ull;
            const ull* wp = swsv + c * 160 + d;
#pragma unroll
            for (int a = 0; a < 10; a++) {
                const ull w = wp[a * 16];
                mA = ff2(aPA[a], w, mA);
                mB = ff2(aPB[a], w, mB);
            }
            float MsA, MvA, MsB, MvB;
            upk2(mA, MsA, MvA);
            upk2(mB, MsB, MvB);

            accS[0] = fmaf(xA.w, MsA, accS[0]);
            aV01[0] = ff2(pk2(xA.x, xA.y), pk2(MvA, MvA), aV01[0]);
            aV2[0]  = fmaf(xA.z, MvA, aV2[0]);
            accS[1] = fmaf(xB.w, MsB, accS[1]);
            aV01[1] = ff2(pk2(xB.x, xB.y), pk2(MvB, MvB), aV01[1]);
            aV2[1]  = fmaf(xB.z, MvB, aV2[1]);
        }

#pragma unroll
        for (int j = 0; j < 2; j++) {
            const int n = nA + j;
            out[O_SC_S + (size_t)n * 64 + D_] = accS[j] * S640;
            float v0, v1; upk2(aV01[j], v0, v1);
            const size_t vb = O_SC_V + (size_t)n * 192 + (size_t)D_ * 3;
            out[vb]     = v0 * S640;
            out[vb + 1] = v1 * S640;
            out[vb + 2] = aV2[j] * S640;
        }
    }
}

// ============================================================================
// K2 v9 (R15): HMMA bf16x3 edge MLP, register-chained layers.
// ============================================================================
#define WPITCH 72

__global__ __launch_bounds__(128, 3) void k_mlp(
    const float* __restrict__ feats, const float* __restrict__ W0)
{
    __shared__ float sW0[512];
    __shared__ __align__(16) __nv_bfloat16 sW1h[64 * WPITCH], sW1l[64 * WPITCH];
    __shared__ __align__(16) __nv_bfloat16 sW2h[64 * WPITCH], sW2l[64 * WPITCH];
    __shared__ float sF[1024];

    const int t = threadIdx.x;
    const int warp = t >> 5, lane = t & 31;
    const int t4 = lane & 3, gid = lane >> 2;

    for (int i = t; i < 512; i += 128) sW0[i] = W0[i];
    for (int i = t; i < 4096; i += 128) {
        const int n = i >> 6, k = i & 63;
        sW1h[n * WPITCH + k] = g_b1h[i];
        sW1l[n * WPITCH + k] = g_b1l[i];
        sW2h[n * WPITCH + k] = g_b2h[i];
        sW2l[n * WPITCH + k] = g_b2l[i];
    }
    const size_t fbase = (size_t)blockIdx.x * 1024;
    for (int i = t; i < 1024; i += 128) sF[i] = feats[fbase + i];
    __syncthreads();

    uint32_t Ah[2][4][4], Al[2][4][4];
#pragma unroll
    for (int mt = 0; mt < 2; mt++) {
#pragma unroll
        for (int row = 0; row < 2; row++) {
            const int el = warp * 32 + mt * 16 + row * 8 + gid;
            const float* f = sF + el * 8;
            float fr[8];
#pragma unroll
            for (int k = 0; k < 8; k++) fr[k] = f[k];
#pragma unroll
            for (int kt = 0; kt < 4; kt++) {
#pragma unroll
                for (int b = 0; b < 2; b++) {
                    const int c0 = kt * 16 + b * 8 + t4 * 2;
                    float h0 = 0.f, h1 = 0.f;
#pragma unroll
                    for (int k = 0; k < 8; k++) {
                        h0 = fmaf(fr[k], sW0[k * 64 + c0], h0);
                        h1 = fmaf(fr[k], sW0[k * 64 + c0 + 1], h1);
                    }
                    h0 = silu_f(h0 * 0.3535533905932738f);
                    h1 = silu_f(h1 * 0.3535533905932738f);
                    splitpack(h0, h1, Ah[mt][kt][row + 2 * b],
                                       Al[mt][kt][row + 2 * b]);
                }
            }
        }
    }

    float D[2][8][4];

#pragma unroll 1
    for (int L = 0; L < 2; L++) {
        const __nv_bfloat16* Wh = L ? sW2h : sW1h;
        const __nv_bfloat16* Wl = L ? sW2l : sW1l;
#pragma unroll
        for (int mt = 0; mt < 2; mt++)
#pragma unroll
            for (int nt = 0; nt < 8; nt++)
#pragma unroll
                for (int q = 0; q < 4; q++) D[mt][nt][q] = 0.f;

#pragma unroll
        for (int nt = 0; nt < 8; nt++) {
            const uint32_t* ph = (const uint32_t*)(Wh + (nt * 8 + gid) * WPITCH);
            const uint32_t* pl = (const uint32_t*)(Wl + (nt * 8 + gid) * WPITCH);
            uint32_t bh[4][2], bl[4][2];
#pragma unroll
            for (int kt = 0; kt < 4; kt++) {
                bh[kt][0] = ph[kt * 8 + t4];  bh[kt][1] = ph[kt * 8 + t4 + 4];
                bl[kt][0] = pl[kt * 8 + t4];  bl[kt][1] = pl[kt * 8 + t4 + 4];
            }
#pragma unroll
            for (int mt = 0; mt < 2; mt++)
#pragma unroll
                for (int kt = 0; kt < 4; kt++) {
                    mma_bf16(D[mt][nt], Ah[mt][kt], bh[kt][0], bh[kt][1]);
                    mma_bf16(D[mt][nt], Ah[mt][kt], bl[kt][0], bl[kt][1]);
                    mma_bf16(D[mt][nt], Al[mt][kt], bh[kt][0], bh[kt][1]);
                }
        }

#pragma unroll
        for (int mt = 0; mt < 2; mt++)
#pragma unroll
            for (int kt = 0; kt < 4; kt++) {
                const float* da = D[mt][2 * kt];
                const float* db = D[mt][2 * kt + 1];
                float v0 = silu_f(da[0] * 0.125f), v1 = silu_f(da[1] * 0.125f);
                splitpack(v0, v1, Ah[mt][kt][0], Al[mt][kt][0]);
                v0 = silu_f(da[2] * 0.125f); v1 = silu_f(da[3] * 0.125f);
                splitpack(v0, v1, Ah[mt][kt][1], Al[mt][kt][1]);
                v0 = silu_f(db[0] * 0.125f); v1 = silu_f(db[1] * 0.125f);
                splitpack(v0, v1, Ah[mt][kt][2], Al[mt][kt][2]);
                v0 = silu_f(db[2] * 0.125f); v1 = silu_f(db[3] * 0.125f);
                splitpack(v0, v1, Ah[mt][kt][3], Al[mt][kt][3]);
            }
    }

    const int eb = blockIdx.x * 128 + warp * 32;
#pragma unroll 1
    for (int ch = 0; ch < 5; ch++) {
        __syncthreads();
        {
            const uint4* p3h = (const uint4*)g_b3h + ch * 512;
            const uint4* p3l = (const uint4*)g_b3l + ch * 512;
#pragma unroll
            for (int it = 0; it < 4; it++) {
                const int i = t + it * 128;
                const int n = i >> 3, q = i & 7;
                const uint32_t boff = n * (WPITCH * 2) + q * 16;
                *(uint4*)((char*)sW1h + boff) = __ldg(p3h + i);
                *(uint4*)((char*)sW1l + boff) = __ldg(p3l + i);
            }
        }
        __syncthreads();

#pragma unroll
        for (int mt = 0; mt < 2; mt++)
#pragma unroll
            for (int nt = 0; nt < 8; nt++)
#pragma unroll
                for (int q = 0; q < 4; q++) D[mt][nt][q] = 0.f;

#pragma unroll
        for (int nt = 0; nt < 8; nt++) {
            const uint32_t* ph = (const uint32_t*)(sW1h + (nt * 8 + gid) * WPITCH);
            const uint32_t* pl = (const uint32_t*)(sW1l + (nt * 8 + gid) * WPITCH);
            uint32_t bh[4][2], bl[4][2];
#pragma unroll
            for (int kt = 0; kt < 4; kt++) {
                bh[kt][0] = ph[kt * 8 + t4];  bh[kt][1] = ph[kt * 8 + t4 + 4];
                bl[kt][0] = pl[kt * 8 + t4];  bl[kt][1] = pl[kt * 8 + t4 + 4];
            }
#pragma unroll
            for (int mt = 0; mt < 2; mt++)
#pragma unroll
                for (int kt = 0; kt < 4; kt++) {
                    mma_bf16(D[mt][nt], Ah[mt][kt], bh[kt][0], bh[kt][1]);
                    mma_bf16(D[mt][nt], Ah[mt][kt], bl[kt][0], bl[kt][1]);
                    mma_bf16(D[mt][nt], Al[mt][kt], bh[kt][0], bh[kt][1]);
                }
        }

#pragma unroll
        for (int mt = 0; mt < 2; mt++) {
            const int e0 = eb + mt * 16 + gid;
#pragma unroll
            for (int nt = 0; nt < 8; nt++) {
                const int col = ch * 64 + nt * 8 + t4 * 2;
                const float* d = D[mt][nt];
                *(float2*)(g_tpw + (size_t)e0 * 320 + col) =
                    make_float2(d[0] * 0.125f, d[1] * 0.125f);
                *(float2*)(g_tpw + (size_t)(e0 + 8) * 320 + col) =
                    make_float2(d[2] * 0.125f, d[3] * 0.125f);
            }
        }
    }
}

// ============================================================================
// CSR build
// ============================================================================
__global__ void k_scan_a() {
    __shared__ int ss[1024];
    const int t = threadIdx.x;
    const int i = blockIdx.x * 1024 + t;
    const int v = g_cnt[i];
    ss[t] = v;
    __syncthreads();
    for (int dd = 1; dd < 1024; dd <<= 1) {
        const int u = (t >= dd) ? ss[t - dd] : 0;
        __syncthreads();
        ss[t] += u;
        __syncthreads();
    }
    g_off[i] = ss[t] - v;
    g_woff[i] = 0;
    if (t == 1023) g_bsum[blockIdx.x] = ss[t];
}
__global__ void k_scan_b() {
    const int t = threadIdx.x;
    const int orig = g_bsum[t];
    int v = orig;
    for (int dd = 1; dd < 32; dd <<= 1) {
        const int u = __shfl_up_sync(0xffffffffu, v, dd);
        if (t >= dd) v += u;
    }
    g_bpre[t] = v - orig;
    if (t == 31) g_off[NN] = v;
}
__global__ void k_scan_c() {
    const int i = blockIdx.x * 256 + threadIdx.x;
    g_off[i] += g_bpre[i >> 10];
}
__global__ void k_fill(const int* __restrict__ recv) {
    const int e = blockIdx.x * blockDim.x + threadIdx.x;
    if (e < EE) {
        const int r = recv[e];
        const int p = atomicAdd(&g_woff[r], 1);
        g_eord[g_off[r] + p] = e;
    }
}
__global__ void k_sort() {
    const int n = blockIdx.x * blockDim.x + threadIdx.x;
    if (n >= NN) return;
    const int s = g_off[n], e = g_off[n + 1];
    for (int i = s + 1; i < e; i++) {
        const int v = g_eord[i];
        int j = i - 1;
        while (j >= s && g_eord[j] > v) { g_eord[j + 1] = g_eord[j]; j--; }
        g_eord[j + 1] = v;
    }
}

// ============================================================================
// K4 v3 (R15): gather aggregation + output GEMMs
// ============================================================================
__global__ __launch_bounds__(256) void k_agg(
    const int* __restrict__ send, const float* __restrict__ eattr,
    float* __restrict__ out)
{
    __shared__ __align__(16) float sms[4][128];
    __shared__ __align__(16) float sv0[4][192];
    __shared__ __align__(16) float sv1[4][192];
    __shared__ __align__(16) float sv2[4][192];

    const int t = threadIdx.x;
    const int g = t >> 6, c = t & 63;
    const int nb = blockIdx.x * 4;
    const int n = nb + g;
    const int e0 = g_off[n], e1 = g_off[n + 1];

    float as0 = 0.f, as1 = 0.f;
    ull   av0_01 = 0ull, av1_01 = 0ull, av2_01 = 0ull;
    float av0_2 = 0.f, av1_2 = 0.f, av2_2 = 0.f;

    for (int p = e0; p < e1; p++) {
        const int e = g_eord[p];
        const int s = __ldg(send + e);
        const float4 ea = __ldg((const float4*)eattr + e);
        const float sh0 = ea.x, s1x = ea.y, s1y = ea.z, s1z = ea.w;
        const float* tp = g_tpw + (size_t)e * 320 + c;
        const float w0 = tp[0], w1 = tp[64], w2 = tp[128], w3 = tp[192], w4 = tp[256];
        const float4 xq = __ldg(g_xq2 + (size_t)s * 64 + c);
        const float xs = xq.w;

        as0 = fmaf(w0 * xs, sh0, as0);
        const float dt = xq.x * s1x + xq.y * s1y + xq.z * s1z;
        as1 = fmaf(w3, dt, as1);

        const float t1 = w1 * xs;
        av0_01 = ff2(pk2(t1, t1), pk2(s1x, s1y), av0_01);
        av0_2  = fmaf(t1, s1z, av0_2);

        const float w2sh = w2 * sh0;
        av1_01 = ff2(pk2(xq.x, xq.y), pk2(w2sh, w2sh), av1_01);
        av1_2  = fmaf(w2sh, xq.z, av1_2);

        const float cx = xq.y * s1z - xq.z * s1y;
        const float cy = xq.z * s1x - xq.x * s1z;
        const float cz = xq.x * s1y - xq.y * s1x;
        av2_01 = ff2(pk2(cx, cy), pk2(w4, w4), av2_01);
        av2_2  = fmaf(w4, cz, av2_2);
    }

    const float INV  = 0.3535533905932738f;
    const float INV3 = INV * 0.5773502691896258f;
    const float INV2 = INV * 0.7071067811865476f;
    sms[g][c]      = as0 * INV;
    sms[g][64 + c] = as1 * INV3;
    {
        float a, b;
        upk2(av0_01, a, b);
        sv0[g][c] = a * INV;  sv1[g][c] = b * INV;  sv2[g][c] = av0_2 * INV;
        upk2(av1_01, a, b);
        sv0[g][64 + c] = a * INV;  sv1[g][64 + c] = b * INV;
        sv2[g][64 + c] = av1_2 * INV;
        upk2(av2_01, a, b);
        sv0[g][128 + c] = a * INV2;  sv1[g][128 + c] = b * INV2;
        sv2[g][128 + c] = av2_2 * INV2;
    }
    __syncthreads();

    if (t < 64) {
        const int d = t;
        ull os[4] = {0ull, 0ull, 0ull, 0ull};
#pragma unroll 4
        for (int kp = 0; kp < 64; kp++) {
            const ull w = __ldg(g_wms2 + kp * 64 + d);
#pragma unroll
            for (int q = 0; q < 4; q++)
                os[q] = ff2(((const ull*)sms[q])[kp], w, os[q]);
        }
#pragma unroll
        for (int q = 0; q < 4; q++)
            out[(size_t)(nb + q) * 64 + d] = fold2(os[q]) * 0.08838834764831845f;
    } else {
        const int u = t - 64;
        const int d = u & 63;
        const int comp = u >> 6;
        const float* pl = (comp == 0) ? &sv0[0][0]
                        : (comp == 1) ? &sv1[0][0] : &sv2[0][0];
        ull ov[4] = {0ull, 0ull, 0ull, 0ull};
#pragma unroll 4
        for (int kp = 0; kp < 96; kp++) {
            const ull w = __ldg(g_wmv2 + kp * 64 + d);
#pragma unroll
            for (int q = 0; q < 4; q++)
                ov[q] = ff2(((const ull*)(pl + q * 192))[kp], w, ov[q]);
        }
        const float S192 = 0.07216878364870323f;
#pragma unroll
        for (int q = 0; q < 4; q++)
            out[O_OUT_V + (size_t)(nb + q) * 192 + (size_t)d * 3 + comp] =
                fold2(ov[q]) * S192;
    }
}

// ============================================================================
// kernel_launch: 3-stream schedule.
//   s0: prep -> mlp -> (wait self+CSR) -> agg -> (wait sc)
//   s1: prepx -> self -> sc   (sc overlaps mlp and agg)
//   s2: (after prepx) scan_a/b/c -> fill -> sort
// ============================================================================
extern "C" void kernel_launch(void* const* d_in, const int* in_sizes, int n_in,
                              void* d_out, int out_size)
{
    const float* node_attrs = (const float*)d_in[0];
    const float* x_s        = (const float*)d_in[1];
    const float* x_v        = (const float*)d_in[2];
    const float* edge_attrs = (const float*)d_in[3];
    const float* edge_feats = (const float*)d_in[4];
    const int*   senders    = (const int*)d_in[5];
    const int*   receivers  = (const int*)d_in[6];
    const float* W_sc_s     = (const float*)d_in[7];
    const float* W_sc_v     = (const float*)d_in[8];
    const float* W_self_s   = (const float*)d_in[9];
    const float* W_self_v   = (const float*)d_in[10];
    const float* mlp_W0     = (const float*)d_in[11];
    const float* mlp_W1     = (const float*)d_in[12];
    const float* mlp_W2     = (const float*)d_in[13];
    const float* mlp_W3     = (const float*)d_in[14];
    const float* W_msg_s    = (const float*)d_in[15];
    const float* W_msg_v    = (const float*)d_in[16];
    float* out = (float*)d_out;

    static cudaStream_t s1 = nullptr, s2 = nullptr;
    static cudaEvent_t evP = nullptr, evX = nullptr, evSelf = nullptr,
                       evCsr = nullptr, evSc = nullptr;
    static bool init_done = false;
    if (!init_done) {
        cudaStreamCreateWithFlags(&s1, cudaStreamNonBlocking);
        cudaStreamCreateWithFlags(&s2, cudaStreamNonBlocking);
        cudaEventCreateWithFlags(&evP,    cudaEventDisableTiming);
        cudaEventCreateWithFlags(&evX,    cudaEventDisableTiming);
        cudaEventCreateWithFlags(&evSelf, cudaEventDisableTiming);
        cudaEventCreateWithFlags(&evCsr,  cudaEventDisableTiming);
        cudaEventCreateWithFlags(&evSc,   cudaEventDisableTiming);
        cudaFuncSetAttribute(k_sc, cudaFuncAttributeMaxDynamicSharedMemorySize,
                             (int)(640 * 16 * 8));
        init_done = true;
    }

    const size_t sc_smem = (size_t)640 * 16 * 8;   // 81920

    // (1) weight prep on s0
    k_prep<<<160, 256, 0, 0>>>(W_sc_s, W_sc_v, W_self_s, W_self_v,
                               W_msg_s, W_msg_v, mlp_W1, mlp_W2, mlp_W3);
    cudaEventRecord(evP, 0);
    cudaStreamWaitEvent(s1, evP, 0);

    // s1: (2) pack+count -> (3) self-mix -> (4) sc  [slot 4 profiled]
    k_prepx<<<NN * 64 / 256, 256, 0, s1>>>(x_s, x_v, receivers);
    cudaEventRecord(evX, s1);
    k_self<<<NN / 4, 256, 0, s1>>>();
    cudaEventRecord(evSelf, s1);
    k_sc<<<dim3(128, 4), 256, sc_smem, s1>>>(node_attrs, out);
    cudaEventRecord(evSc, s1);

    // s0: (5) HMMA MLP
    k_mlp<<<EE / 128, 128, 0, 0>>>(edge_feats, mlp_W0);

    // s2: CSR chain after prepx
    cudaStreamWaitEvent(s2, evX, 0);
    k_scan_a<<<32, 1024, 0, s2>>>();
    k_scan_b<<<1, 32, 0, s2>>>();
    k_scan_c<<<128, 256, 0, s2>>>();
    k_fill<<<EE / 256, 256, 0, s2>>>(receivers);
    k_sort<<<NN / 128, 128, 0, s2>>>();
    cudaEventRecord(evCsr, s2);

    // s0: join (self + CSR; mlp ordered on s0) -> agg; then join sc.
    cudaStreamWaitEvent(0, evSelf, 0);
    cudaStreamWaitEvent(0, evCsr, 0);
    k_agg<<<NN / 4, 256, 0, 0>>>(senders, edge_attrs, out);
    cudaStreamWaitEvent(0, evSc, 0);
}